// round 10
// baseline (speedup 1.0000x reference)
#include <cuda_runtime.h>
#include <math.h>

#define BZ   4
#define QL   512
#define CL   1536
#define KVL  2048
#define E    1024
#define NH   16
#define HD   64
#define MROWS (BZ*QL)   // 2048

#define OUT_K ((size_t)MROWS*E)                       // 2097152
#define OUT_V (OUT_K + (size_t)BZ*KVL*E)              // 10485760

// ---------------- scratch (tf32 stored as u32) -------------------------------
__device__ unsigned g_xt [MROWS*E];       // X  tf32
__device__ unsigned g_wqt[E*E];           // Wq tf32 [n][k]
__device__ unsigned g_wkt[E*E];
__device__ unsigned g_wvt[E*E];
__device__ unsigned g_wot[E*E];
__device__ unsigned g_q  [MROWS*E];       // Q proj, tf32, pre-scaled by 1/8
__device__ unsigned g_ctx[MROWS*E];       // attention ctx, tf32
__device__ unsigned g_kt [(size_t)BZ*KVL*E];  // full K (cache+new), tf32
__device__ unsigned g_vt [(size_t)BZ*KVL*E];  // full V, tf32

// ---------------- helpers ----------------------------------------------------
__device__ __forceinline__ unsigned f2tf(float f) {
    unsigned u;
    asm("cvt.rna.tf32.f32 %0, %1;" : "=r"(u) : "f"(f));
    return u;
}

__device__ __forceinline__ void mma8(float* c,
                                     unsigned a0, unsigned a1, unsigned a2, unsigned a3,
                                     unsigned b0, unsigned b1)
{
    asm volatile(
        "mma.sync.aligned.m16n8k8.row.col.f32.tf32.tf32.f32 "
        "{%0,%1,%2,%3}, {%4,%5,%6,%7}, {%8,%9}, {%0,%1,%2,%3};\n"
        : "+f"(c[0]), "+f"(c[1]), "+f"(c[2]), "+f"(c[3])
        : "r"(a0), "r"(a1), "r"(a2), "r"(a3), "r"(b0), "r"(b1));
}

#define CP16(dst, src) \
    asm volatile("cp.async.cg.shared.global [%0], [%1], 16;\n" \
                 :: "r"(dst), "l"(src))
#define CPCOMMIT() asm volatile("cp.async.commit_group;\n" ::: "memory")
#define CPWAIT(n)  asm volatile("cp.async.wait_group %0;\n" :: "n"(n) : "memory")

// ---------------- convert inputs to tf32 -------------------------------------
__global__ void convert_tf32(const float4* __restrict__ X,
                             const float4* __restrict__ Wq,
                             const float4* __restrict__ Wk,
                             const float4* __restrict__ Wv,
                             const float4* __restrict__ Wo)
{
    int i = blockIdx.x*256 + threadIdx.x;
    const float4* src; uint4* dst; int off;
    if (i < 524288)       { src = X;  dst = (uint4*)g_xt;  off = i; }
    else if (i < 786432)  { src = Wq; dst = (uint4*)g_wqt; off = i - 524288; }
    else if (i < 1048576) { src = Wk; dst = (uint4*)g_wkt; off = i - 786432; }
    else if (i < 1310720) { src = Wv; dst = (uint4*)g_wvt; off = i - 1048576; }
    else                  { src = Wo; dst = (uint4*)g_wot; off = i - 1310720; }
    float4 v = src[off];
    uint4 u;
    u.x = f2tf(v.x); u.y = f2tf(v.y); u.z = f2tf(v.z); u.w = f2tf(v.w);
    dst[off] = u;
}

// ---------------- cache copy: f32 to dout + tf32 to g_kt/g_vt ----------------
__global__ void copy_cache(const float4* __restrict__ kc,
                           const float4* __restrict__ vc,
                           float* __restrict__ dout)
{
    const int per_b = CL*E/4;
    int idx = blockIdx.x*blockDim.x + threadIdx.x;
    if (idx >= BZ*per_b) return;
    int b = idx / per_b, rem = idx - b*per_b;
    size_t d = (size_t)b*(KVL*E/4) + rem;
    float4 k4 = kc[idx], v4 = vc[idx];
    ((float4*)(dout + OUT_K))[d] = k4;
    ((float4*)(dout + OUT_V))[d] = v4;
    uint4 u;
    u.x=f2tf(k4.x); u.y=f2tf(k4.y); u.z=f2tf(k4.z); u.w=f2tf(k4.w);
    ((uint4*)g_kt)[d] = u;
    u.x=f2tf(v4.x); u.y=f2tf(v4.y); u.z=f2tf(v4.z); u.w=f2tf(v4.w);
    ((uint4*)g_vt)[d] = u;
}

// ---------------- tf32 GEMM core (cp.async, 4-stage, 1 barrier/iter) ---------
// BM=128, BN=128, BK=16, 256 thr, warp grid 2x4, warp tile 64x32, stride 20.
// Stage written at iter kt is (kt+3)%4 == (kt-1)%4: all warps finished reading
// it before this iteration's barrier -> single __syncthreads per iteration.
// One commit group per iteration (empty at the tail) keeps wait_group(2) exact.
#define GST 20
#define GSTAGES 4
#define GSTAGE_WORDS (2*128*GST)
#define GEMM_SMEM (GSTAGES*GSTAGE_WORDS*4)   // 81920 bytes

__device__ __forceinline__
void gemm_core(const unsigned* __restrict__ AGLOB,
               const unsigned* __restrict__ BGLOB,
               int bm, int nrow0, float acc[4][4][4])
{
    extern __shared__ __align__(16) unsigned sAB[];
    unsigned sbase = (unsigned)__cvta_generic_to_shared(sAB);

    int tid = threadIdx.x;
    int warp = tid >> 5, lane = tid & 31, g = lane >> 2, tig = lane & 3;
    int wm = (warp >> 2)*64, wn = (warp & 3)*32;
    int r0c = tid >> 2, c0c = (tid & 3)*4;
    int r1c = r0c + 64;

    auto issue = [&](int st, int k0) {
        unsigned ab = sbase + (unsigned)(st*GSTAGE_WORDS*4);
        unsigned bb = ab + (unsigned)(128*GST*4);
        CP16(ab + (unsigned)((r0c*GST + c0c)*4),
             AGLOB + (size_t)(bm + r0c)*E + k0 + c0c);
        CP16(ab + (unsigned)((r1c*GST + c0c)*4),
             AGLOB + (size_t)(bm + r1c)*E + k0 + c0c);
        CP16(bb + (unsigned)((r0c*GST + c0c)*4),
             BGLOB + (size_t)(nrow0 + r0c)*E + k0 + c0c);
        CP16(bb + (unsigned)((r1c*GST + c0c)*4),
             BGLOB + (size_t)(nrow0 + r1c)*E + k0 + c0c);
    };

    #pragma unroll
    for (int mt = 0; mt < 4; mt++)
        #pragma unroll
        for (int nt = 0; nt < 4; nt++)
            #pragma unroll
            for (int i = 0; i < 4; i++) acc[mt][nt][i] = 0.f;

    issue(0, 0);  CPCOMMIT();
    issue(1, 16); CPCOMMIT();
    issue(2, 32); CPCOMMIT();

    for (int kt = 0; kt < 64; kt++) {
        CPWAIT(2);
        __syncthreads();

        // prefetch next stage immediately (overlaps with compute below)
        if (kt + 3 < 64) issue((kt+3) & 3, (kt+3)*16);
        CPCOMMIT();

        const unsigned* As = sAB + (kt & 3)*GSTAGE_WORDS;
        const unsigned* Bs = As + 128*GST;

        #pragma unroll
        for (int kh = 0; kh < 2; kh++) {
            int kb = kh*8;
            unsigned af[4][4], bf[4][2];
            #pragma unroll
            for (int mt = 0; mt < 4; mt++) {
                int r = wm + mt*16;
                af[mt][0] = As[(r+g  )*GST + kb + tig];
                af[mt][1] = As[(r+g+8)*GST + kb + tig];
                af[mt][2] = As[(r+g  )*GST + kb + tig + 4];
                af[mt][3] = As[(r+g+8)*GST + kb + tig + 4];
            }
            #pragma unroll
            for (int nt = 0; nt < 4; nt++) {
                int cidx = wn + nt*8 + g;
                bf[nt][0] = Bs[cidx*GST + kb + tig];
                bf[nt][1] = Bs[cidx*GST + kb + tig + 4];
            }
            #pragma unroll
            for (int mt = 0; mt < 4; mt++)
                #pragma unroll
                for (int nt = 0; nt < 4; nt++)
                    mma8(acc[mt][nt], af[mt][0], af[mt][1], af[mt][2],
                         af[mt][3], bf[nt][0], bf[nt][1]);
        }
    }
}

// ---------------- QKV projection ---------------------------------------------
__global__ __launch_bounds__(256, 2)
void gemm_qkv(const float* __restrict__ bq, const float* __restrict__ bk,
              const float* __restrict__ bv, float* __restrict__ dout)
{
    int bn = blockIdx.x*128, bm = blockIdx.y*128;
    int seg = bn >> 10;            // 0=Q 1=K 2=V
    int nrow0 = bn & (E-1);
    const unsigned* Bglob = (seg == 0) ? g_wqt : (seg == 1) ? g_wkt : g_wvt;
    const float*    bias  = (seg == 0) ? bq   : (seg == 1) ? bk    : bv;

    float acc[4][4][4];
    gemm_core(g_xt, Bglob, bm, nrow0, acc);

    int tid = threadIdx.x;
    int warp = tid >> 5, lane = tid & 31, g = lane >> 2, tig = lane & 3;
    int wm = (warp >> 2)*64, wn = (warp & 3)*32;

    #pragma unroll
    for (int mt = 0; mt < 4; mt++) {
        int m = bm + wm + mt*16 + g;
        #pragma unroll
        for (int nt = 0; nt < 4; nt++) {
            int nl = nrow0 + wn + nt*8 + 2*tig;
            float b0 = bias[nl], b1 = bias[nl+1];
            float v0 = acc[mt][nt][0] + b0, v1 = acc[mt][nt][1] + b1;
            float v2 = acc[mt][nt][2] + b0, v3 = acc[mt][nt][3] + b1;
            if (seg == 0) {
                uint2 u0; u0.x = f2tf(v0*0.125f); u0.y = f2tf(v1*0.125f);
                uint2 u1; u1.x = f2tf(v2*0.125f); u1.y = f2tf(v3*0.125f);
                *(uint2*)&g_q[(size_t)m*E + nl]     = u0;
                *(uint2*)&g_q[(size_t)(m+8)*E + nl] = u1;
            } else {
                float* fbase = dout + (seg == 1 ? OUT_K : OUT_V);
                unsigned* tbase = (seg == 1) ? g_kt : g_vt;
                int ba = m >> 9,      t0 = m & 511;
                int bb = (m+8) >> 9,  t1 = (m+8) & 511;
                size_t ra = ((size_t)(ba*KVL) + CL + t0)*E + nl;
                size_t rb = ((size_t)(bb*KVL) + CL + t1)*E + nl;
                *(float2*)&fbase[ra] = make_float2(v0, v1);
                *(float2*)&fbase[rb] = make_float2(v2, v3);
                uint2 u0; u0.x = f2tf(v0); u0.y = f2tf(v1);
                uint2 u1; u1.x = f2tf(v2); u1.y = f2tf(v3);
                *(uint2*)&tbase[ra] = u0;
                *(uint2*)&tbase[rb] = u1;
            }
        }
    }
}

// ---------------- output projection ------------------------------------------
__global__ __launch_bounds__(256, 2)
void gemm_out(const float* __restrict__ bo, float* __restrict__ dout)
{
    int bn = blockIdx.x*128, bm = blockIdx.y*128;

    float acc[4][4][4];
    gemm_core(g_ctx, g_wot, bm, bn, acc);

    int tid = threadIdx.x;
    int warp = tid >> 5, lane = tid & 31, g = lane >> 2, tig = lane & 3;
    int wm = (warp >> 2)*64, wn = (warp & 3)*32;

    #pragma unroll
    for (int mt = 0; mt < 4; mt++) {
        int m = bm + wm + mt*16 + g;
        #pragma unroll
        for (int nt = 0; nt < 4; nt++) {
            int n = bn + wn + nt*8 + 2*tig;
            float b0 = bo[n], b1 = bo[n+1];
            *(float2*)&dout[(size_t)m*E + n] =
                make_float2(acc[mt][nt][0] + b0, acc[mt][nt][1] + b1);
            *(float2*)&dout[(size_t)(m+8)*E + n] =
                make_float2(acc[mt][nt][2] + b0, acc[mt][nt][3] + b1);
        }
    }
}

// ---------------- flash attention (tf32, cp.async, shfl-P) -- R6 version -----
#define SWK(r,d) ((d) ^ ((((unsigned)(r))&7u)<<2))
#define SWV(r,d) ((d) ^ ((((unsigned)(r))&3u)<<3))

__global__ __launch_bounds__(128)
void attn(const float* __restrict__ amask)
{
    __shared__ __align__(16) unsigned sK[2][64*64];
    __shared__ __align__(16) unsigned sV[64*64];

    int qt = blockIdx.x, h = blockIdx.y, b = blockIdx.z;
    int tid  = threadIdx.x;
    int warp = tid >> 5, lane = tid & 31, g = lane >> 2, tig = lane & 3;
    int m0 = warp*16;

    unsigned kAddr[2], vAddr;
    kAddr[0] = (unsigned)__cvta_generic_to_shared(sK[0]);
    kAddr[1] = (unsigned)__cvta_generic_to_shared(sK[1]);
    vAddr    = (unsigned)__cvta_generic_to_shared(sV);

    const unsigned* kg = g_kt + ((size_t)b*KVL)*E + h*HD;
    const unsigned* vg = g_vt + ((size_t)b*KVL)*E + h*HD;

    auto issueK = [&](int tile, int st) {
        const unsigned* src = kg + (size_t)tile*64*E;
        #pragma unroll
        for (int i = 0; i < 8; i++) {
            int c = tid + i*128;
            int row = c >> 4, c4 = (c & 15)*4;
            CP16(kAddr[st] + (unsigned)((row*64 + SWK(row, c4))*4),
                 src + (size_t)row*E + c4);
        }
    };
    auto issueV = [&](int tile) {
        const unsigned* src = vg + (size_t)tile*64*E;
        #pragma unroll
        for (int i = 0; i < 8; i++) {
            int c = tid + i*128;
            int row = c >> 4, c4 = (c & 15)*4;
            CP16(vAddr + (unsigned)((row*64 + SWV(row, c4))*4),
                 src + (size_t)row*E + c4);
        }
    };

    unsigned qf[8][4];
    {
        const unsigned* qb = g_q + ((size_t)(b*QL + qt*64))*E + h*HD;
        #pragma unroll
        for (int kc = 0; kc < 8; kc++) {
            int kb = kc*8;
            qf[kc][0] = __ldg(qb + (size_t)(m0+g  )*E + kb + tig);
            qf[kc][1] = __ldg(qb + (size_t)(m0+g+8)*E + kb + tig);
            qf[kc][2] = __ldg(qb + (size_t)(m0+g  )*E + kb + tig + 4);
            qf[kc][3] = __ldg(qb + (size_t)(m0+g+8)*E + kb + tig + 4);
        }
    }

    float O[8][4];
    #pragma unroll
    for (int nt = 0; nt < 8; nt++)
        #pragma unroll
        for (int i = 0; i < 4; i++) O[nt][i] = 0.f;
    float mi0 = -1e30f, mi1 = -1e30f, li0 = 0.f, li1 = 0.f;

    int nkt = 25 + qt;
    issueK(0, 0); CPCOMMIT();

    for (int kt = 0; kt < nkt; kt++) {
        int cur = kt & 1;
        if (kt) __syncthreads();
        issueV(kt); CPCOMMIT();
        if (kt + 1 < nkt) {
            issueK(kt+1, 1-cur); CPCOMMIT();
            CPWAIT(2);
        } else {
            CPWAIT(1);
        }
        __syncthreads();

        // ---- S = (Q/8) K^T ----
        float s[8][4];
        #pragma unroll
        for (int nt = 0; nt < 8; nt++)
            #pragma unroll
            for (int i = 0; i < 4; i++) s[nt][i] = 0.f;
        #pragma unroll
        for (int kc = 0; kc < 8; kc++) {
            int kb = kc*8;
            #pragma unroll
            for (int nt = 0; nt < 8; nt++) {
                int col = nt*8 + g;
                unsigned b0 = sK[cur][col*64 + SWK(col, kb+tig)];
                unsigned b1 = sK[cur][col*64 + SWK(col, kb+tig+4)];
                mma8(s[nt], qf[kc][0], qf[kc][1], qf[kc][2], qf[kc][3], b0, b1);
            }
        }

        // ---- mask + online softmax ----
        int c0 = kt*64;
        const float* am = amask + (size_t)b*(CL+QL) + c0;
        bool last = (kt == nkt-1);
        #pragma unroll
        for (int nt = 0; nt < 8; nt++) {
            int j0 = nt*8 + 2*tig, j1 = j0 + 1;
            float a0 = __ldg(am + j0), a1 = __ldg(am + j1);
            s[nt][0] += a0; s[nt][1] += a1; s[nt][2] += a0; s[nt][3] += a1;
            if (last) {
                int r0 = m0 + g, r1 = r0 + 8;
                if (j0 > r0) s[nt][0] = -1e30f;
                if (j1 > r0) s[nt][1] = -1e30f;
                if (j0 > r1) s[nt][2] = -1e30f;
                if (j1 > r1) s[nt][3] = -1e30f;
            }
        }

        float mx0 = -1e30f, mx1 = -1e30f;
        #pragma unroll
        for (int nt = 0; nt < 8; nt++) {
            mx0 = fmaxf(mx0, fmaxf(s[nt][0], s[nt][1]));
            mx1 = fmaxf(mx1, fmaxf(s[nt][2], s[nt][3]));
        }
        mx0 = fmaxf(mx0, __shfl_xor_sync(0xffffffffu, mx0, 1));
        mx0 = fmaxf(mx0, __shfl_xor_sync(0xffffffffu, mx0, 2));
        mx1 = fmaxf(mx1, __shfl_xor_sync(0xffffffffu, mx1, 1));
        mx1 = fmaxf(mx1, __shfl_xor_sync(0xffffffffu, mx1, 2));

        float mn0 = fmaxf(mi0, mx0), mn1 = fmaxf(mi1, mx1);
        float cor0 = __expf(mi0 - mn0), cor1 = __expf(mi1 - mn1);
        mi0 = mn0; mi1 = mn1;

        float sum0 = 0.f, sum1 = 0.f;
        #pragma unroll
        for (int nt = 0; nt < 8; nt++) {
            s[nt][0] = __expf(s[nt][0] - mn0); sum0 += s[nt][0];
            s[nt][1] = __expf(s[nt][1] - mn0); sum0 += s[nt][1];
            s[nt][2] = __expf(s[nt][2] - mn1); sum1 += s[nt][2];
            s[nt][3] = __expf(s[nt][3] - mn1); sum1 += s[nt][3];
        }
        sum0 += __shfl_xor_sync(0xffffffffu, sum0, 1);
        sum0 += __shfl_xor_sync(0xffffffffu, sum0, 2);
        sum1 += __shfl_xor_sync(0xffffffffu, sum1, 1);
        sum1 += __shfl_xor_sync(0xffffffffu, sum1, 2);
        li0 = li0*cor0 + sum0;
        li1 = li1*cor1 + sum1;
        #pragma unroll
        for (int nt = 0; nt < 8; nt++) {
            O[nt][0] *= cor0; O[nt][1] *= cor0;
            O[nt][2] *= cor1; O[nt][3] *= cor1;
        }

        if (kt + 1 < nkt) { CPWAIT(1); } else { CPWAIT(0); }
        __syncthreads();

        // ---- O += P V  (P via cvt + shfl permutation; no smem round-trip) ----
        int l1 = (lane & 28) + (tig >> 1);
        int l2 = l1 + 2;
        bool odd = (tig & 1);
        #pragma unroll
        for (int kc = 0; kc < 8; kc++) {
            unsigned u0 = f2tf(s[kc][0]), u1 = f2tf(s[kc][1]);
            unsigned u2 = f2tf(s[kc][2]), u3 = f2tf(s[kc][3]);
            unsigned s00 = __shfl_sync(0xffffffffu, u0, l1);
            unsigned s01 = __shfl_sync(0xffffffffu, u1, l1);
            unsigned s02 = __shfl_sync(0xffffffffu, u2, l1);
            unsigned s03 = __shfl_sync(0xffffffffu, u3, l1);
            unsigned s10 = __shfl_sync(0xffffffffu, u0, l2);
            unsigned s11 = __shfl_sync(0xffffffffu, u1, l2);
            unsigned s12 = __shfl_sync(0xffffffffu, u2, l2);
            unsigned s13 = __shfl_sync(0xffffffffu, u3, l2);
            unsigned a0 = odd ? s01 : s00;
            unsigned a1 = odd ? s03 : s02;
            unsigned a2 = odd ? s11 : s10;
            unsigned a3 = odd ? s13 : s12;
            int kb = kc*8;
            #pragma unroll
            for (int nt = 0; nt < 8; nt++) {
                int dcol = nt*8 + g;
                unsigned b0 = sV[(kb+tig  )*64 + SWV(kb+tig,   dcol)];
                unsigned b1 = sV[(kb+tig+4)*64 + SWV(kb+tig+4, dcol)];
                mma8(O[nt], a0, a1, a2, a3, b0, b1);
            }
        }
    }

    // ---- write ctx (tf32) ----
    float inv0 = 1.f/li0, inv1 = 1.f/li1;
    int r0 = b*QL + qt*64 + m0 + g;
    #pragma unroll
    for (int nt = 0; nt < 8; nt++) {
        int col = h*HD + nt*8 + 2*tig;
        uint2 u0; u0.x = f2tf(O[nt][0]*inv0); u0.y = f2tf(O[nt][1]*inv0);
        uint2 u1; u1.x = f2tf(O[nt][2]*inv1); u1.y = f2tf(O[nt][3]*inv1);
        *(uint2*)&g_ctx[(size_t)r0*E + col]     = u0;
        *(uint2*)&g_ctx[(size_t)(r0+8)*E + col] = u1;
    }
}

// ---------------- launch ----------------------------------------------------
extern "C" void kernel_launch(void* const* d_in, const int* in_sizes, int n_in,
                              void* d_out, int out_size)
{
    const float* X     = (const float*)d_in[0];
    const float* amask = (const float*)d_in[1];
    const float* kc    = (const float*)d_in[2];
    const float* vc    = (const float*)d_in[3];
    const float* Wq    = (const float*)d_in[4];
    const float* bq    = (const float*)d_in[5];
    const float* Wk    = (const float*)d_in[6];
    const float* bk    = (const float*)d_in[7];
    const float* Wv    = (const float*)d_in[8];
    const float* bv    = (const float*)d_in[9];
    const float* Wo    = (const float*)d_in[10];
    const float* bo    = (const float*)d_in[11];
    float* out = (float*)d_out;

    static bool attr_done = false;
    if (!attr_done) {
        cudaFuncSetAttribute(gemm_qkv,
            cudaFuncAttributeMaxDynamicSharedMemorySize, GEMM_SMEM);
        cudaFuncSetAttribute(gemm_out,
            cudaFuncAttributeMaxDynamicSharedMemorySize, GEMM_SMEM);
        attr_done = true;
    }

    convert_tf32<<<6144, 256>>>((const float4*)X, (const float4*)Wq,
                                (const float4*)Wk, (const float4*)Wv,
                                (const float4*)Wo);
    {
        int total = BZ*CL*E/4;
        copy_cache<<<(total + 255)/256, 256>>>((const float4*)kc,
                                               (const float4*)vc, out);
    }
    {
        dim3 grid(3*E/128, MROWS/128);       // 24 x 16
        gemm_qkv<<<grid, 256, GEMM_SMEM>>>(bq, bk, bv, out);
    }
    {
        dim3 grid(QL/64, NH, BZ);            // 8 x 16 x 4
        attn<<<grid, 128>>>(amask);
    }
    {
        dim3 grid(E/128, MROWS/128);         // 8 x 16
        gemm_out<<<grid, 256, GEMM_SMEM>>>(bo, out);
    }
}

// round 11
// speedup vs baseline: 1.3261x; 1.3261x over previous
#include <cuda_runtime.h>
#include <math.h>

#define BZ   4
#define QL   512
#define CL   1536
#define KVL  2048
#define E    1024
#define NH   16
#define HD   64
#define MROWS (BZ*QL)   // 2048

#define OUT_K ((size_t)MROWS*E)                       // 2097152
#define OUT_V (OUT_K + (size_t)BZ*KVL*E)              // 10485760

// ---------------- scratch (tf32 stored as u32) -------------------------------
__device__ unsigned g_xt [MROWS*E];       // X  tf32
__device__ unsigned g_wqt[E*E];           // Wq tf32 [n][k]
__device__ unsigned g_wkt[E*E];
__device__ unsigned g_wvt[E*E];
__device__ unsigned g_wot[E*E];
__device__ unsigned g_q  [MROWS*E];       // Q proj, tf32, pre-scaled by 1/8
__device__ unsigned g_ctx[MROWS*E];       // attention ctx, tf32
__device__ unsigned g_kt [(size_t)BZ*KVL*E];  // full K (cache+new), tf32
__device__ unsigned g_vt [(size_t)BZ*KVL*E];  // full V, tf32

// ---------------- helpers ----------------------------------------------------
__device__ __forceinline__ unsigned f2tf(float f) {
    unsigned u;
    asm("cvt.rna.tf32.f32 %0, %1;" : "=r"(u) : "f"(f));
    return u;
}

__device__ __forceinline__ void mma8(float* c,
                                     unsigned a0, unsigned a1, unsigned a2, unsigned a3,
                                     unsigned b0, unsigned b1)
{
    asm volatile(
        "mma.sync.aligned.m16n8k8.row.col.f32.tf32.tf32.f32 "
        "{%0,%1,%2,%3}, {%4,%5,%6,%7}, {%8,%9}, {%0,%1,%2,%3};\n"
        : "+f"(c[0]), "+f"(c[1]), "+f"(c[2]), "+f"(c[3])
        : "r"(a0), "r"(a1), "r"(a2), "r"(a3), "r"(b0), "r"(b1));
}

#define CP16(dst, src) \
    asm volatile("cp.async.cg.shared.global [%0], [%1], 16;\n" \
                 :: "r"(dst), "l"(src))
#define CPCOMMIT() asm volatile("cp.async.commit_group;\n" ::: "memory")
#define CPWAIT(n)  asm volatile("cp.async.wait_group %0;\n" :: "n"(n) : "memory")

// ---------------- convert inputs to tf32 -------------------------------------
__global__ void convert_tf32(const float4* __restrict__ X,
                             const float4* __restrict__ Wq,
                             const float4* __restrict__ Wk,
                             const float4* __restrict__ Wv,
                             const float4* __restrict__ Wo)
{
    int i = blockIdx.x*256 + threadIdx.x;
    const float4* src; uint4* dst; int off;
    if (i < 524288)       { src = X;  dst = (uint4*)g_xt;  off = i; }
    else if (i < 786432)  { src = Wq; dst = (uint4*)g_wqt; off = i - 524288; }
    else if (i < 1048576) { src = Wk; dst = (uint4*)g_wkt; off = i - 786432; }
    else if (i < 1310720) { src = Wv; dst = (uint4*)g_wvt; off = i - 1048576; }
    else                  { src = Wo; dst = (uint4*)g_wot; off = i - 1310720; }
    float4 v = src[off];
    uint4 u;
    u.x = f2tf(v.x); u.y = f2tf(v.y); u.z = f2tf(v.z); u.w = f2tf(v.w);
    dst[off] = u;
}

// ---------------- cache copy: f32 to dout + tf32 to g_kt/g_vt ----------------
__global__ void copy_cache(const float4* __restrict__ kc,
                           const float4* __restrict__ vc,
                           float* __restrict__ dout)
{
    const int per_b = CL*E/4;
    int idx = blockIdx.x*blockDim.x + threadIdx.x;
    if (idx >= BZ*per_b) return;
    int b = idx / per_b, rem = idx - b*per_b;
    size_t d = (size_t)b*(KVL*E/4) + rem;
    float4 k4 = kc[idx], v4 = vc[idx];
    ((float4*)(dout + OUT_K))[d] = k4;
    ((float4*)(dout + OUT_V))[d] = v4;
    uint4 u;
    u.x=f2tf(k4.x); u.y=f2tf(k4.y); u.z=f2tf(k4.z); u.w=f2tf(k4.w);
    ((uint4*)g_kt)[d] = u;
    u.x=f2tf(v4.x); u.y=f2tf(v4.y); u.z=f2tf(v4.z); u.w=f2tf(v4.w);
    ((uint4*)g_vt)[d] = u;
}

// ---------------- tf32 GEMM core (cp.async, 2-stage) -------------------------
// BM=64, BN=128, BK=16, 256 thr, warp grid 2x4, warp tile 32x32, stride 20.
// Smaller BM doubles the grid (5+ blocks/SM) to fix grid-limited occupancy.
#define GST 20
#define GSTAGE (192*GST)      // (64 A-rows + 128 B-rows) * GST words

__device__ __forceinline__
void gemm_core(const unsigned* __restrict__ AGLOB,
               const unsigned* __restrict__ BGLOB,
               int bm, int nrow0, float acc[2][4][4])
{
    __shared__ __align__(16) unsigned sAB[2*GSTAGE];
    unsigned* Asm[2] = { sAB,          sAB + GSTAGE };
    unsigned* Bsm[2] = { sAB + 64*GST, sAB + GSTAGE + 64*GST };
    unsigned aAddr[2], bAddr[2];
    aAddr[0] = (unsigned)__cvta_generic_to_shared(Asm[0]);
    aAddr[1] = (unsigned)__cvta_generic_to_shared(Asm[1]);
    bAddr[0] = (unsigned)__cvta_generic_to_shared(Bsm[0]);
    bAddr[1] = (unsigned)__cvta_generic_to_shared(Bsm[1]);

    int tid = threadIdx.x;
    int warp = tid >> 5, lane = tid & 31, g = lane >> 2, tig = lane & 3;
    int wm = (warp >> 2)*32, wn = (warp & 3)*32;
    int r0c = tid >> 2, c0c = (tid & 3)*4;     // rows 0..63, col4 0..12
    int r1c = r0c + 64;

    auto issue = [&](int st, int k0) {
        CP16(aAddr[st] + (unsigned)((r0c*GST + c0c)*4),
             AGLOB + (size_t)(bm + r0c)*E + k0 + c0c);
        CP16(bAddr[st] + (unsigned)((r0c*GST + c0c)*4),
             BGLOB + (size_t)(nrow0 + r0c)*E + k0 + c0c);
        CP16(bAddr[st] + (unsigned)((r1c*GST + c0c)*4),
             BGLOB + (size_t)(nrow0 + r1c)*E + k0 + c0c);
    };

    #pragma unroll
    for (int mt = 0; mt < 2; mt++)
        #pragma unroll
        for (int nt = 0; nt < 4; nt++)
            #pragma unroll
            for (int i = 0; i < 4; i++) acc[mt][nt][i] = 0.f;

    issue(0, 0);  CPCOMMIT();
    issue(1, 16); CPCOMMIT();

    for (int kt = 0; kt < 64; kt++) {
        int cur = kt & 1;
        if (kt < 63) { CPWAIT(1); } else { CPWAIT(0); }
        __syncthreads();
        #pragma unroll
        for (int kh = 0; kh < 2; kh++) {
            int kb = kh*8;
            unsigned af[2][4], bf[4][2];
            #pragma unroll
            for (int mt = 0; mt < 2; mt++) {
                int r = wm + mt*16;
                af[mt][0] = Asm[cur][(r+g  )*GST + kb + tig];
                af[mt][1] = Asm[cur][(r+g+8)*GST + kb + tig];
                af[mt][2] = Asm[cur][(r+g  )*GST + kb + tig + 4];
                af[mt][3] = Asm[cur][(r+g+8)*GST + kb + tig + 4];
            }
            #pragma unroll
            for (int nt = 0; nt < 4; nt++) {
                int cidx = wn + nt*8 + g;
                bf[nt][0] = Bsm[cur][cidx*GST + kb + tig];
                bf[nt][1] = Bsm[cur][cidx*GST + kb + tig + 4];
            }
            #pragma unroll
            for (int mt = 0; mt < 2; mt++)
                #pragma unroll
                for (int nt = 0; nt < 4; nt++)
                    mma8(acc[mt][nt], af[mt][0], af[mt][1], af[mt][2],
                         af[mt][3], bf[nt][0], bf[nt][1]);
        }
        __syncthreads();
        if (kt + 2 < 64) { issue(cur, (kt+2)*16); CPCOMMIT(); }
    }
}

// ---------------- QKV projection ---------------------------------------------
__global__ __launch_bounds__(256)
void gemm_qkv(const float* __restrict__ bq, const float* __restrict__ bk,
              const float* __restrict__ bv, float* __restrict__ dout)
{
    int bn = blockIdx.x*128, bm = blockIdx.y*64;
    int seg = bn >> 10;            // 0=Q 1=K 2=V
    int nrow0 = bn & (E-1);
    const unsigned* Bglob = (seg == 0) ? g_wqt : (seg == 1) ? g_wkt : g_wvt;
    const float*    bias  = (seg == 0) ? bq   : (seg == 1) ? bk    : bv;

    float acc[2][4][4];
    gemm_core(g_xt, Bglob, bm, nrow0, acc);

    int tid = threadIdx.x;
    int warp = tid >> 5, lane = tid & 31, g = lane >> 2, tig = lane & 3;
    int wm = (warp >> 2)*32, wn = (warp & 3)*32;

    #pragma unroll
    for (int mt = 0; mt < 2; mt++) {
        int m = bm + wm + mt*16 + g;
        #pragma unroll
        for (int nt = 0; nt < 4; nt++) {
            int nl = nrow0 + wn + nt*8 + 2*tig;
            float b0 = bias[nl], b1 = bias[nl+1];
            float v0 = acc[mt][nt][0] + b0, v1 = acc[mt][nt][1] + b1;
            float v2 = acc[mt][nt][2] + b0, v3 = acc[mt][nt][3] + b1;
            if (seg == 0) {
                uint2 u0; u0.x = f2tf(v0*0.125f); u0.y = f2tf(v1*0.125f);
                uint2 u1; u1.x = f2tf(v2*0.125f); u1.y = f2tf(v3*0.125f);
                *(uint2*)&g_q[(size_t)m*E + nl]     = u0;
                *(uint2*)&g_q[(size_t)(m+8)*E + nl] = u1;
            } else {
                float* fbase = dout + (seg == 1 ? OUT_K : OUT_V);
                unsigned* tbase = (seg == 1) ? g_kt : g_vt;
                int ba = m >> 9,      t0 = m & 511;
                int bb = (m+8) >> 9,  t1 = (m+8) & 511;
                size_t ra = ((size_t)(ba*KVL) + CL + t0)*E + nl;
                size_t rb = ((size_t)(bb*KVL) + CL + t1)*E + nl;
                *(float2*)&fbase[ra] = make_float2(v0, v1);
                *(float2*)&fbase[rb] = make_float2(v2, v3);
                uint2 u0; u0.x = f2tf(v0); u0.y = f2tf(v1);
                uint2 u1; u1.x = f2tf(v2); u1.y = f2tf(v3);
                *(uint2*)&tbase[ra] = u0;
                *(uint2*)&tbase[rb] = u1;
            }
        }
    }
}

// ---------------- output projection ------------------------------------------
__global__ __launch_bounds__(256)
void gemm_out(const float* __restrict__ bo, float* __restrict__ dout)
{
    int bn = blockIdx.x*128, bm = blockIdx.y*64;

    float acc[2][4][4];
    gemm_core(g_ctx, g_wot, bm, bn, acc);

    int tid = threadIdx.x;
    int warp = tid >> 5, lane = tid & 31, g = lane >> 2, tig = lane & 3;
    int wm = (warp >> 2)*32, wn = (warp & 3)*32;

    #pragma unroll
    for (int mt = 0; mt < 2; mt++) {
        int m = bm + wm + mt*16 + g;
        #pragma unroll
        for (int nt = 0; nt < 4; nt++) {
            int n = bn + wn + nt*8 + 2*tig;
            float b0 = bo[n], b1 = bo[n+1];
            *(float2*)&dout[(size_t)m*E + n] =
                make_float2(acc[mt][nt][0] + b0, acc[mt][nt][1] + b1);
            *(float2*)&dout[(size_t)(m+8)*E + n] =
                make_float2(acc[mt][nt][2] + b0, acc[mt][nt][3] + b1);
        }
    }
}

// ---------------- flash attention (tf32, cp.async, shfl-P) -- R6 exact -------
#define SWK(r,d) ((d) ^ ((((unsigned)(r))&7u)<<2))
#define SWV(r,d) ((d) ^ ((((unsigned)(r))&3u)<<3))

__global__ __launch_bounds__(128)
void attn(const float* __restrict__ amask)
{
    __shared__ __align__(16) unsigned sK[2][64*64];
    __shared__ __align__(16) unsigned sV[64*64];

    int qt = blockIdx.x, h = blockIdx.y, b = blockIdx.z;
    int tid  = threadIdx.x;
    int warp = tid >> 5, lane = tid & 31, g = lane >> 2, tig = lane & 3;
    int m0 = warp*16;

    unsigned kAddr[2], vAddr;
    kAddr[0] = (unsigned)__cvta_generic_to_shared(sK[0]);
    kAddr[1] = (unsigned)__cvta_generic_to_shared(sK[1]);
    vAddr    = (unsigned)__cvta_generic_to_shared(sV);

    const unsigned* kg = g_kt + ((size_t)b*KVL)*E + h*HD;
    const unsigned* vg = g_vt + ((size_t)b*KVL)*E + h*HD;

    auto issueK = [&](int tile, int st) {
        const unsigned* src = kg + (size_t)tile*64*E;
        #pragma unroll
        for (int i = 0; i < 8; i++) {
            int c = tid + i*128;
            int row = c >> 4, c4 = (c & 15)*4;
            CP16(kAddr[st] + (unsigned)((row*64 + SWK(row, c4))*4),
                 src + (size_t)row*E + c4);
        }
    };
    auto issueV = [&](int tile) {
        const unsigned* src = vg + (size_t)tile*64*E;
        #pragma unroll
        for (int i = 0; i < 8; i++) {
            int c = tid + i*128;
            int row = c >> 4, c4 = (c & 15)*4;
            CP16(vAddr + (unsigned)((row*64 + SWV(row, c4))*4),
                 src + (size_t)row*E + c4);
        }
    };

    unsigned qf[8][4];
    {
        const unsigned* qb = g_q + ((size_t)(b*QL + qt*64))*E + h*HD;
        #pragma unroll
        for (int kc = 0; kc < 8; kc++) {
            int kb = kc*8;
            qf[kc][0] = __ldg(qb + (size_t)(m0+g  )*E + kb + tig);
            qf[kc][1] = __ldg(qb + (size_t)(m0+g+8)*E + kb + tig);
            qf[kc][2] = __ldg(qb + (size_t)(m0+g  )*E + kb + tig + 4);
            qf[kc][3] = __ldg(qb + (size_t)(m0+g+8)*E + kb + tig + 4);
        }
    }

    float O[8][4];
    #pragma unroll
    for (int nt = 0; nt < 8; nt++)
        #pragma unroll
        for (int i = 0; i < 4; i++) O[nt][i] = 0.f;
    float mi0 = -1e30f, mi1 = -1e30f, li0 = 0.f, li1 = 0.f;

    int nkt = 25 + qt;
    issueK(0, 0); CPCOMMIT();

    for (int kt = 0; kt < nkt; kt++) {
        int cur = kt & 1;
        if (kt) __syncthreads();
        issueV(kt); CPCOMMIT();
        if (kt + 1 < nkt) {
            issueK(kt+1, 1-cur); CPCOMMIT();
            CPWAIT(2);
        } else {
            CPWAIT(1);
        }
        __syncthreads();

        // ---- S = (Q/8) K^T ----
        float s[8][4];
        #pragma unroll
        for (int nt = 0; nt < 8; nt++)
            #pragma unroll
            for (int i = 0; i < 4; i++) s[nt][i] = 0.f;
        #pragma unroll
        for (int kc = 0; kc < 8; kc++) {
            int kb = kc*8;
            #pragma unroll
            for (int nt = 0; nt < 8; nt++) {
                int col = nt*8 + g;
                unsigned b0 = sK[cur][col*64 + SWK(col, kb+tig)];
                unsigned b1 = sK[cur][col*64 + SWK(col, kb+tig+4)];
                mma8(s[nt], qf[kc][0], qf[kc][1], qf[kc][2], qf[kc][3], b0, b1);
            }
        }

        // ---- mask + online softmax ----
        int c0 = kt*64;
        const float* am = amask + (size_t)b*(CL+QL) + c0;
        bool last = (kt == nkt-1);
        #pragma unroll
        for (int nt = 0; nt < 8; nt++) {
            int j0 = nt*8 + 2*tig, j1 = j0 + 1;
            float a0 = __ldg(am + j0), a1 = __ldg(am + j1);
            s[nt][0] += a0; s[nt][1] += a1; s[nt][2] += a0; s[nt][3] += a1;
            if (last) {
                int r0 = m0 + g, r1 = r0 + 8;
                if (j0 > r0) s[nt][0] = -1e30f;
                if (j1 > r0) s[nt][1] = -1e30f;
                if (j0 > r1) s[nt][2] = -1e30f;
                if (j1 > r1) s[nt][3] = -1e30f;
            }
        }

        float mx0 = -1e30f, mx1 = -1e30f;
        #pragma unroll
        for (int nt = 0; nt < 8; nt++) {
            mx0 = fmaxf(mx0, fmaxf(s[nt][0], s[nt][1]));
            mx1 = fmaxf(mx1, fmaxf(s[nt][2], s[nt][3]));
        }
        mx0 = fmaxf(mx0, __shfl_xor_sync(0xffffffffu, mx0, 1));
        mx0 = fmaxf(mx0, __shfl_xor_sync(0xffffffffu, mx0, 2));
        mx1 = fmaxf(mx1, __shfl_xor_sync(0xffffffffu, mx1, 1));
        mx1 = fmaxf(mx1, __shfl_xor_sync(0xffffffffu, mx1, 2));

        float mn0 = fmaxf(mi0, mx0), mn1 = fmaxf(mi1, mx1);
        float cor0 = __expf(mi0 - mn0), cor1 = __expf(mi1 - mn1);
        mi0 = mn0; mi1 = mn1;

        float sum0 = 0.f, sum1 = 0.f;
        #pragma unroll
        for (int nt = 0; nt < 8; nt++) {
            s[nt][0] = __expf(s[nt][0] - mn0); sum0 += s[nt][0];
            s[nt][1] = __expf(s[nt][1] - mn0); sum0 += s[nt][1];
            s[nt][2] = __expf(s[nt][2] - mn1); sum1 += s[nt][2];
            s[nt][3] = __expf(s[nt][3] - mn1); sum1 += s[nt][3];
        }
        sum0 += __shfl_xor_sync(0xffffffffu, sum0, 1);
        sum0 += __shfl_xor_sync(0xffffffffu, sum0, 2);
        sum1 += __shfl_xor_sync(0xffffffffu, sum1, 1);
        sum1 += __shfl_xor_sync(0xffffffffu, sum1, 2);
        li0 = li0*cor0 + sum0;
        li1 = li1*cor1 + sum1;
        #pragma unroll
        for (int nt = 0; nt < 8; nt++) {
            O[nt][0] *= cor0; O[nt][1] *= cor0;
            O[nt][2] *= cor1; O[nt][3] *= cor1;
        }

        if (kt + 1 < nkt) { CPWAIT(1); } else { CPWAIT(0); }
        __syncthreads();

        // ---- O += P V  (P via cvt + shfl permutation; no smem round-trip) ----
        int l1 = (lane & 28) + (tig >> 1);
        int l2 = l1 + 2;
        bool odd = (tig & 1);
        #pragma unroll
        for (int kc = 0; kc < 8; kc++) {
            unsigned u0 = f2tf(s[kc][0]), u1 = f2tf(s[kc][1]);
            unsigned u2 = f2tf(s[kc][2]), u3 = f2tf(s[kc][3]);
            unsigned s00 = __shfl_sync(0xffffffffu, u0, l1);
            unsigned s01 = __shfl_sync(0xffffffffu, u1, l1);
            unsigned s02 = __shfl_sync(0xffffffffu, u2, l1);
            unsigned s03 = __shfl_sync(0xffffffffu, u3, l1);
            unsigned s10 = __shfl_sync(0xffffffffu, u0, l2);
            unsigned s11 = __shfl_sync(0xffffffffu, u1, l2);
            unsigned s12 = __shfl_sync(0xffffffffu, u2, l2);
            unsigned s13 = __shfl_sync(0xffffffffu, u3, l2);
            unsigned a0 = odd ? s01 : s00;
            unsigned a1 = odd ? s03 : s02;
            unsigned a2 = odd ? s11 : s10;
            unsigned a3 = odd ? s13 : s12;
            int kb = kc*8;
            #pragma unroll
            for (int nt = 0; nt < 8; nt++) {
                int dcol = nt*8 + g;
                unsigned b0 = sV[(kb+tig  )*64 + SWV(kb+tig,   dcol)];
                unsigned b1 = sV[(kb+tig+4)*64 + SWV(kb+tig+4, dcol)];
                mma8(O[nt], a0, a1, a2, a3, b0, b1);
            }
        }
    }

    // ---- write ctx (tf32) ----
    float inv0 = 1.f/li0, inv1 = 1.f/li1;
    int r0 = b*QL + qt*64 + m0 + g;
    #pragma unroll
    for (int nt = 0; nt < 8; nt++) {
        int col = h*HD + nt*8 + 2*tig;
        uint2 u0; u0.x = f2tf(O[nt][0]*inv0); u0.y = f2tf(O[nt][1]*inv0);
        uint2 u1; u1.x = f2tf(O[nt][2]*inv1); u1.y = f2tf(O[nt][3]*inv1);
        *(uint2*)&g_ctx[(size_t)r0*E + col]     = u0;
        *(uint2*)&g_ctx[(size_t)(r0+8)*E + col] = u1;
    }
}

// ---------------- launch ----------------------------------------------------
extern "C" void kernel_launch(void* const* d_in, const int* in_sizes, int n_in,
                              void* d_out, int out_size)
{
    const float* X     = (const float*)d_in[0];
    const float* amask = (const float*)d_in[1];
    const float* kc    = (const float*)d_in[2];
    const float* vc    = (const float*)d_in[3];
    const float* Wq    = (const float*)d_in[4];
    const float* bq    = (const float*)d_in[5];
    const float* Wk    = (const float*)d_in[6];
    const float* bk    = (const float*)d_in[7];
    const float* Wv    = (const float*)d_in[8];
    const float* bv    = (const float*)d_in[9];
    const float* Wo    = (const float*)d_in[10];
    const float* bo    = (const float*)d_in[11];
    float* out = (float*)d_out;

    convert_tf32<<<6144, 256>>>((const float4*)X, (const float4*)Wq,
                                (const float4*)Wk, (const float4*)Wv,
                                (const float4*)Wo);
    {
        int total = BZ*CL*E/4;
        copy_cache<<<(total + 255)/256, 256>>>((const float4*)kc,
                                               (const float4*)vc, out);
    }
    {
        dim3 grid(3*E/128, MROWS/64);        // 24 x 32 = 768 blocks
        gemm_qkv<<<grid, 256>>>(bq, bk, bv, out);
    }
    {
        dim3 grid(QL/64, NH, BZ);            // 8 x 16 x 4
        attn<<<grid, 128>>>(amask);
    }
    {
        dim3 grid(E/128, MROWS/64);          // 8 x 32 = 256 blocks
        gemm_out<<<grid, 256>>>(bo, out);
    }
}

// round 12
// speedup vs baseline: 1.5435x; 1.1640x over previous
#include <cuda_runtime.h>
#include <math.h>

#define BZ   4
#define QL   512
#define CL   1536
#define KVL  2048
#define E    1024
#define NH   16
#define HD   64
#define MROWS (BZ*QL)   // 2048

#define OUT_K ((size_t)MROWS*E)                       // 2097152
#define OUT_V (OUT_K + (size_t)BZ*KVL*E)              // 10485760

#define PO_ROWS (BZ*NH*QL)    // 32768

// ---------------- scratch (tf32 stored as u32) -------------------------------
__device__ unsigned g_xt [MROWS*E];       // X  tf32
__device__ unsigned g_wqt[E*E];           // Wq tf32 [n][k]
__device__ unsigned g_wkt[E*E];
__device__ unsigned g_wvt[E*E];
__device__ unsigned g_wot[E*E];
__device__ unsigned g_q  [MROWS*E];       // Q proj, tf32, pre-scaled by 1/8
__device__ unsigned g_ctx[MROWS*E];       // attention ctx, tf32
__device__ unsigned g_kt [(size_t)BZ*KVL*E];  // full K (cache+new), tf32
__device__ unsigned g_vt [(size_t)BZ*KVL*E];  // full V, tf32

// split-KV partials
__device__ float g_po[(size_t)2*PO_ROWS*HD];  // unnormalized partial O
__device__ float g_pm[2*PO_ROWS];             // row max
__device__ float g_pl[2*PO_ROWS];             // row sum

// ---------------- helpers ----------------------------------------------------
__device__ __forceinline__ unsigned f2tf(float f) {
    unsigned u;
    asm("cvt.rna.tf32.f32 %0, %1;" : "=r"(u) : "f"(f));
    return u;
}

__device__ __forceinline__ void mma8(float* c,
                                     unsigned a0, unsigned a1, unsigned a2, unsigned a3,
                                     unsigned b0, unsigned b1)
{
    asm volatile(
        "mma.sync.aligned.m16n8k8.row.col.f32.tf32.tf32.f32 "
        "{%0,%1,%2,%3}, {%4,%5,%6,%7}, {%8,%9}, {%0,%1,%2,%3};\n"
        : "+f"(c[0]), "+f"(c[1]), "+f"(c[2]), "+f"(c[3])
        : "r"(a0), "r"(a1), "r"(a2), "r"(a3), "r"(b0), "r"(b1));
}

#define CP16(dst, src) \
    asm volatile("cp.async.cg.shared.global [%0], [%1], 16;\n" \
                 :: "r"(dst), "l"(src))
#define CPCOMMIT() asm volatile("cp.async.commit_group;\n" ::: "memory")
#define CPWAIT(n)  asm volatile("cp.async.wait_group %0;\n" :: "n"(n) : "memory")

// ---------------- convert inputs to tf32 -------------------------------------
__global__ void convert_tf32(const float4* __restrict__ X,
                             const float4* __restrict__ Wq,
                             const float4* __restrict__ Wk,
                             const float4* __restrict__ Wv,
                             const float4* __restrict__ Wo)
{
    int i = blockIdx.x*256 + threadIdx.x;
    const float4* src; uint4* dst; int off;
    if (i < 524288)       { src = X;  dst = (uint4*)g_xt;  off = i; }
    else if (i < 786432)  { src = Wq; dst = (uint4*)g_wqt; off = i - 524288; }
    else if (i < 1048576) { src = Wk; dst = (uint4*)g_wkt; off = i - 786432; }
    else if (i < 1310720) { src = Wv; dst = (uint4*)g_wvt; off = i - 1048576; }
    else                  { src = Wo; dst = (uint4*)g_wot; off = i - 1310720; }
    float4 v = src[off];
    uint4 u;
    u.x = f2tf(v.x); u.y = f2tf(v.y); u.z = f2tf(v.z); u.w = f2tf(v.w);
    dst[off] = u;
}

// ---------------- cache copy: f32 to dout + tf32 to g_kt/g_vt ----------------
__global__ void copy_cache(const float4* __restrict__ kc,
                           const float4* __restrict__ vc,
                           float* __restrict__ dout)
{
    const int per_b = CL*E/4;
    int idx = blockIdx.x*blockDim.x + threadIdx.x;
    if (idx >= BZ*per_b) return;
    int b = idx / per_b, rem = idx - b*per_b;
    size_t d = (size_t)b*(KVL*E/4) + rem;
    float4 k4 = kc[idx], v4 = vc[idx];
    ((float4*)(dout + OUT_K))[d] = k4;
    ((float4*)(dout + OUT_V))[d] = v4;
    uint4 u;
    u.x=f2tf(k4.x); u.y=f2tf(k4.y); u.z=f2tf(k4.z); u.w=f2tf(k4.w);
    ((uint4*)g_kt)[d] = u;
    u.x=f2tf(v4.x); u.y=f2tf(v4.y); u.z=f2tf(v4.z); u.w=f2tf(v4.w);
    ((uint4*)g_vt)[d] = u;
}

// ---------------- tf32 GEMM core (cp.async, 2-stage) -------------------------
// BM=64, BN=128, BK=16, 256 thr, warp grid 2x4, warp tile 32x32, stride 20.
#define GST 20
#define GSTAGE (192*GST)      // (64 A-rows + 128 B-rows) * GST words

__device__ __forceinline__
void gemm_core(const unsigned* __restrict__ AGLOB,
               const unsigned* __restrict__ BGLOB,
               int bm, int nrow0, float acc[2][4][4])
{
    __shared__ __align__(16) unsigned sAB[2*GSTAGE];
    unsigned* Asm[2] = { sAB,          sAB + GSTAGE };
    unsigned* Bsm[2] = { sAB + 64*GST, sAB + GSTAGE + 64*GST };
    unsigned aAddr[2], bAddr[2];
    aAddr[0] = (unsigned)__cvta_generic_to_shared(Asm[0]);
    aAddr[1] = (unsigned)__cvta_generic_to_shared(Asm[1]);
    bAddr[0] = (unsigned)__cvta_generic_to_shared(Bsm[0]);
    bAddr[1] = (unsigned)__cvta_generic_to_shared(Bsm[1]);

    int tid = threadIdx.x;
    int warp = tid >> 5, lane = tid & 31, g = lane >> 2, tig = lane & 3;
    int wm = (warp >> 2)*32, wn = (warp & 3)*32;
    int r0c = tid >> 2, c0c = (tid & 3)*4;     // rows 0..63, col4 0..12
    int r1c = r0c + 64;

    auto issue = [&](int st, int k0) {
        CP16(aAddr[st] + (unsigned)((r0c*GST + c0c)*4),
             AGLOB + (size_t)(bm + r0c)*E + k0 + c0c);
        CP16(bAddr[st] + (unsigned)((r0c*GST + c0c)*4),
             BGLOB + (size_t)(nrow0 + r0c)*E + k0 + c0c);
        CP16(bAddr[st] + (unsigned)((r1c*GST + c0c)*4),
             BGLOB + (size_t)(nrow0 + r1c)*E + k0 + c0c);
    };

    #pragma unroll
    for (int mt = 0; mt < 2; mt++)
        #pragma unroll
        for (int nt = 0; nt < 4; nt++)
            #pragma unroll
            for (int i = 0; i < 4; i++) acc[mt][nt][i] = 0.f;

    issue(0, 0);  CPCOMMIT();
    issue(1, 16); CPCOMMIT();

    for (int kt = 0; kt < 64; kt++) {
        int cur = kt & 1;
        if (kt < 63) { CPWAIT(1); } else { CPWAIT(0); }
        __syncthreads();
        #pragma unroll
        for (int kh = 0; kh < 2; kh++) {
            int kb = kh*8;
            unsigned af[2][4], bf[4][2];
            #pragma unroll
            for (int mt = 0; mt < 2; mt++) {
                int r = wm + mt*16;
                af[mt][0] = Asm[cur][(r+g  )*GST + kb + tig];
                af[mt][1] = Asm[cur][(r+g+8)*GST + kb + tig];
                af[mt][2] = Asm[cur][(r+g  )*GST + kb + tig + 4];
                af[mt][3] = Asm[cur][(r+g+8)*GST + kb + tig + 4];
            }
            #pragma unroll
            for (int nt = 0; nt < 4; nt++) {
                int cidx = wn + nt*8 + g;
                bf[nt][0] = Bsm[cur][cidx*GST + kb + tig];
                bf[nt][1] = Bsm[cur][cidx*GST + kb + tig + 4];
            }
            #pragma unroll
            for (int mt = 0; mt < 2; mt++)
                #pragma unroll
                for (int nt = 0; nt < 4; nt++)
                    mma8(acc[mt][nt], af[mt][0], af[mt][1], af[mt][2],
                         af[mt][3], bf[nt][0], bf[nt][1]);
        }
        __syncthreads();
        if (kt + 2 < 64) { issue(cur, (kt+2)*16); CPCOMMIT(); }
    }
}

// ---------------- QKV projection ---------------------------------------------
__global__ __launch_bounds__(256)
void gemm_qkv(const float* __restrict__ bq, const float* __restrict__ bk,
              const float* __restrict__ bv, float* __restrict__ dout)
{
    int bn = blockIdx.x*128, bm = blockIdx.y*64;
    int seg = bn >> 10;            // 0=Q 1=K 2=V
    int nrow0 = bn & (E-1);
    const unsigned* Bglob = (seg == 0) ? g_wqt : (seg == 1) ? g_wkt : g_wvt;
    const float*    bias  = (seg == 0) ? bq   : (seg == 1) ? bk    : bv;

    float acc[2][4][4];
    gemm_core(g_xt, Bglob, bm, nrow0, acc);

    int tid = threadIdx.x;
    int warp = tid >> 5, lane = tid & 31, g = lane >> 2, tig = lane & 3;
    int wm = (warp >> 2)*32, wn = (warp & 3)*32;

    #pragma unroll
    for (int mt = 0; mt < 2; mt++) {
        int m = bm + wm + mt*16 + g;
        #pragma unroll
        for (int nt = 0; nt < 4; nt++) {
            int nl = nrow0 + wn + nt*8 + 2*tig;
            float b0 = bias[nl], b1 = bias[nl+1];
            float v0 = acc[mt][nt][0] + b0, v1 = acc[mt][nt][1] + b1;
            float v2 = acc[mt][nt][2] + b0, v3 = acc[mt][nt][3] + b1;
            if (seg == 0) {
                uint2 u0; u0.x = f2tf(v0*0.125f); u0.y = f2tf(v1*0.125f);
                uint2 u1; u1.x = f2tf(v2*0.125f); u1.y = f2tf(v3*0.125f);
                *(uint2*)&g_q[(size_t)m*E + nl]     = u0;
                *(uint2*)&g_q[(size_t)(m+8)*E + nl] = u1;
            } else {
                float* fbase = dout + (seg == 1 ? OUT_K : OUT_V);
                unsigned* tbase = (seg == 1) ? g_kt : g_vt;
                int ba = m >> 9,      t0 = m & 511;
                int bb = (m+8) >> 9,  t1 = (m+8) & 511;
                size_t ra = ((size_t)(ba*KVL) + CL + t0)*E + nl;
                size_t rb = ((size_t)(bb*KVL) + CL + t1)*E + nl;
                *(float2*)&fbase[ra] = make_float2(v0, v1);
                *(float2*)&fbase[rb] = make_float2(v2, v3);
                uint2 u0; u0.x = f2tf(v0); u0.y = f2tf(v1);
                uint2 u1; u1.x = f2tf(v2); u1.y = f2tf(v3);
                *(uint2*)&tbase[ra] = u0;
                *(uint2*)&tbase[rb] = u1;
            }
        }
    }
}

// ---------------- output projection ------------------------------------------
__global__ __launch_bounds__(256)
void gemm_out(const float* __restrict__ bo, float* __restrict__ dout)
{
    int bn = blockIdx.x*128, bm = blockIdx.y*64;

    float acc[2][4][4];
    gemm_core(g_ctx, g_wot, bm, bn, acc);

    int tid = threadIdx.x;
    int warp = tid >> 5, lane = tid & 31, g = lane >> 2, tig = lane & 3;
    int wm = (warp >> 2)*32, wn = (warp & 3)*32;

    #pragma unroll
    for (int mt = 0; mt < 2; mt++) {
        int m = bm + wm + mt*16 + g;
        #pragma unroll
        for (int nt = 0; nt < 4; nt++) {
            int n = bn + wn + nt*8 + 2*tig;
            float b0 = bo[n], b1 = bo[n+1];
            *(float2*)&dout[(size_t)m*E + n] =
                make_float2(acc[mt][nt][0] + b0, acc[mt][nt][1] + b1);
            *(float2*)&dout[(size_t)(m+8)*E + n] =
                make_float2(acc[mt][nt][2] + b0, acc[mt][nt][3] + b1);
        }
    }
}

// ---------------- flash attention: static 2-way split-KV, Q in SMEM ----------
// Grid (16,16,4): x = qt*2+chunk. 128 thr, 4 warps x 16 q-rows.
// SMEM: sQ + sK + sV = 48KB static, single-buffered.
// K(t+1) issued after S-barrier, V(t+1) after PV-barrier (one group/tile).
// Partials (unnormalized O, m, l) merged exactly by combine_attn.
#define SWK(r,d) ((d) ^ ((((unsigned)(r))&7u)<<2))
#define SWV(r,d) ((d) ^ ((((unsigned)(r))&3u)<<3))

__global__ __launch_bounds__(128, 4)
void attn(const float* __restrict__ amask)
{
    __shared__ __align__(16) unsigned sQ[64*64];
    __shared__ __align__(16) unsigned sK[64*64];
    __shared__ __align__(16) unsigned sV[64*64];

    int qt    = blockIdx.x >> 1;
    int chunk = blockIdx.x & 1;
    int h = blockIdx.y, b = blockIdx.z;

    int tid  = threadIdx.x;
    int warp = tid >> 5, lane = tid & 31, g = lane >> 2, tig = lane & 3;
    int m0 = warp*16;

    int nkt  = 25 + qt;
    int half = nkt >> 1;
    int t0   = chunk ? half : 0;
    int ntiles = chunk ? (nkt - half) : half;

    unsigned qAddr = (unsigned)__cvta_generic_to_shared(sQ);
    unsigned kAddr = (unsigned)__cvta_generic_to_shared(sK);
    unsigned vAddr = (unsigned)__cvta_generic_to_shared(sV);

    const unsigned* kg = g_kt + ((size_t)b*KVL)*E + h*HD;
    const unsigned* vg = g_vt + ((size_t)b*KVL)*E + h*HD;

    auto issueK = [&](int tile) {
        const unsigned* src = kg + (size_t)tile*64*E;
        #pragma unroll
        for (int i = 0; i < 8; i++) {
            int c = tid + i*128;
            int row = c >> 4, c4 = (c & 15)*4;
            CP16(kAddr + (unsigned)((row*64 + SWK(row, c4))*4),
                 src + (size_t)row*E + c4);
        }
    };
    auto issueV = [&](int tile) {
        const unsigned* src = vg + (size_t)tile*64*E;
        #pragma unroll
        for (int i = 0; i < 8; i++) {
            int c = tid + i*128;
            int row = c >> 4, c4 = (c & 15)*4;
            CP16(vAddr + (unsigned)((row*64 + SWV(row, c4))*4),
                 src + (size_t)row*E + c4);
        }
    };

    // prologue: Q tile + first K,V — one commit group
    {
        const unsigned* src = g_q + ((size_t)(b*QL + qt*64))*E + h*HD;
        #pragma unroll
        for (int i = 0; i < 8; i++) {
            int c = tid + i*128;
            int row = c >> 4, c4 = (c & 15)*4;
            CP16(qAddr + (unsigned)((row*64 + SWK(row, c4))*4),
                 src + (size_t)row*E + c4);
        }
    }
    issueK(t0);
    issueV(t0);
    CPCOMMIT();

    float O[8][4];
    #pragma unroll
    for (int nt = 0; nt < 8; nt++)
        #pragma unroll
        for (int i = 0; i < 4; i++) O[nt][i] = 0.f;
    float mi0 = -1e30f, mi1 = -1e30f, li0 = 0.f, li1 = 0.f;

    for (int it = 0; it < ntiles; it++) {
        int kt = t0 + it;
        CPWAIT(0);
        __syncthreads();

        // ---- S = (Q/8) K^T  (Q fragments straight from sQ) ----
        float s[8][4];
        #pragma unroll
        for (int nt = 0; nt < 8; nt++)
            #pragma unroll
            for (int i = 0; i < 4; i++) s[nt][i] = 0.f;
        #pragma unroll
        for (int kc = 0; kc < 8; kc++) {
            int kb = kc*8;
            unsigned a0 = sQ[(m0+g  )*64 + SWK(m0+g,   kb+tig)];
            unsigned a1 = sQ[(m0+g+8)*64 + SWK(m0+g+8, kb+tig)];
            unsigned a2 = sQ[(m0+g  )*64 + SWK(m0+g,   kb+tig+4)];
            unsigned a3 = sQ[(m0+g+8)*64 + SWK(m0+g+8, kb+tig+4)];
            #pragma unroll
            for (int nt = 0; nt < 8; nt++) {
                int col = nt*8 + g;
                unsigned b0 = sK[col*64 + SWK(col, kb+tig)];
                unsigned b1 = sK[col*64 + SWK(col, kb+tig+4)];
                mma8(s[nt], a0, a1, a2, a3, b0, b1);
            }
        }

        __syncthreads();                         // sK fully consumed
        if (it + 1 < ntiles) issueK(kt+1);       // K prefetch hides behind softmax+PV

        // ---- mask + online softmax ----
        int c0 = kt*64;
        const float* am = amask + (size_t)b*(CL+QL) + c0;
        bool causal = (chunk == 1) && (it == ntiles-1);
        #pragma unroll
        for (int nt = 0; nt < 8; nt++) {
            int j0 = nt*8 + 2*tig, j1 = j0 + 1;
            float a0 = __ldg(am + j0), a1 = __ldg(am + j1);
            s[nt][0] += a0; s[nt][1] += a1; s[nt][2] += a0; s[nt][3] += a1;
            if (causal) {
                int r0 = CL + qt*64 + m0 + g, r1 = r0 + 8;
                int cj0 = c0 + j0, cj1 = c0 + j1;
                if (cj0 > r0) s[nt][0] = -1e30f;
                if (cj1 > r0) s[nt][1] = -1e30f;
                if (cj0 > r1) s[nt][2] = -1e30f;
                if (cj1 > r1) s[nt][3] = -1e30f;
            }
        }

        float mx0 = -1e30f, mx1 = -1e30f;
        #pragma unroll
        for (int nt = 0; nt < 8; nt++) {
            mx0 = fmaxf(mx0, fmaxf(s[nt][0], s[nt][1]));
            mx1 = fmaxf(mx1, fmaxf(s[nt][2], s[nt][3]));
        }
        mx0 = fmaxf(mx0, __shfl_xor_sync(0xffffffffu, mx0, 1));
        mx0 = fmaxf(mx0, __shfl_xor_sync(0xffffffffu, mx0, 2));
        mx1 = fmaxf(mx1, __shfl_xor_sync(0xffffffffu, mx1, 1));
        mx1 = fmaxf(mx1, __shfl_xor_sync(0xffffffffu, mx1, 2));

        float mn0 = fmaxf(mi0, mx0), mn1 = fmaxf(mi1, mx1);
        float cor0 = __expf(mi0 - mn0), cor1 = __expf(mi1 - mn1);
        mi0 = mn0; mi1 = mn1;

        float sum0 = 0.f, sum1 = 0.f;
        #pragma unroll
        for (int nt = 0; nt < 8; nt++) {
            s[nt][0] = __expf(s[nt][0] - mn0); sum0 += s[nt][0];
            s[nt][1] = __expf(s[nt][1] - mn0); sum0 += s[nt][1];
            s[nt][2] = __expf(s[nt][2] - mn1); sum1 += s[nt][2];
            s[nt][3] = __expf(s[nt][3] - mn1); sum1 += s[nt][3];
        }
        sum0 += __shfl_xor_sync(0xffffffffu, sum0, 1);
        sum0 += __shfl_xor_sync(0xffffffffu, sum0, 2);
        sum1 += __shfl_xor_sync(0xffffffffu, sum1, 1);
        sum1 += __shfl_xor_sync(0xffffffffu, sum1, 2);
        li0 = li0*cor0 + sum0;
        li1 = li1*cor1 + sum1;
        #pragma unroll
        for (int nt = 0; nt < 8; nt++) {
            O[nt][0] *= cor0; O[nt][1] *= cor0;
            O[nt][2] *= cor1; O[nt][3] *= cor1;
        }

        // ---- O += P V  (P via cvt + shfl permutation; no smem round-trip) ----
        int l1 = (lane & 28) + (tig >> 1);
        int l2 = l1 + 2;
        bool odd = (tig & 1);
        #pragma unroll
        for (int kc = 0; kc < 8; kc++) {
            unsigned u0 = f2tf(s[kc][0]), u1 = f2tf(s[kc][1]);
            unsigned u2 = f2tf(s[kc][2]), u3 = f2tf(s[kc][3]);
            unsigned s00 = __shfl_sync(0xffffffffu, u0, l1);
            unsigned s01 = __shfl_sync(0xffffffffu, u1, l1);
            unsigned s02 = __shfl_sync(0xffffffffu, u2, l1);
            unsigned s03 = __shfl_sync(0xffffffffu, u3, l1);
            unsigned s10 = __shfl_sync(0xffffffffu, u0, l2);
            unsigned s11 = __shfl_sync(0xffffffffu, u1, l2);
            unsigned s12 = __shfl_sync(0xffffffffu, u2, l2);
            unsigned s13 = __shfl_sync(0xffffffffu, u3, l2);
            unsigned a0 = odd ? s01 : s00;
            unsigned a1 = odd ? s03 : s02;
            unsigned a2 = odd ? s11 : s10;
            unsigned a3 = odd ? s13 : s12;
            int kb = kc*8;
            #pragma unroll
            for (int nt = 0; nt < 8; nt++) {
                int dcol = nt*8 + g;
                unsigned b0 = sV[(kb+tig  )*64 + SWV(kb+tig,   dcol)];
                unsigned b1 = sV[(kb+tig+4)*64 + SWV(kb+tig+4, dcol)];
                mma8(O[nt], a0, a1, a2, a3, b0, b1);
            }
        }

        __syncthreads();                          // sV fully consumed
        if (it + 1 < ntiles) issueV(kt+1);
        CPCOMMIT();                               // group = K(t+1)+V(t+1)
    }

    // ---- write partials (unnormalized O, m, l) ----
    size_t rowbase = ((size_t)(b*NH + h))*QL + qt*64;
    float* po = g_po + ((size_t)chunk*PO_ROWS + rowbase)*HD;
    #pragma unroll
    for (int nt = 0; nt < 8; nt++) {
        int col = nt*8 + 2*tig;
        *(float2*)&po[(size_t)(m0+g)*HD + col]   = make_float2(O[nt][0], O[nt][1]);
        *(float2*)&po[(size_t)(m0+g+8)*HD + col] = make_float2(O[nt][2], O[nt][3]);
    }
    if (tig == 0) {
        size_t mb = (size_t)chunk*PO_ROWS + rowbase;
        g_pm[mb + m0 + g]     = mi0;
        g_pl[mb + m0 + g]     = li0;
        g_pm[mb + m0 + g + 8] = mi1;
        g_pl[mb + m0 + g + 8] = li1;
    }
}

// ---------------- combine split-KV partials -> ctx (tf32) --------------------
__global__ void combine_attn()
{
    int idx = blockIdx.x*256 + threadIdx.x;      // 0 .. 524287
    int d4  = idx & 15;
    int row = idx >> 4;                          // 0 .. 32767

    float m0 = g_pm[row], m1 = g_pm[PO_ROWS + row];
    float l0 = g_pl[row], l1 = g_pl[PO_ROWS + row];
    float m  = fmaxf(m0, m1);
    float w0 = __expf(m0 - m), w1 = __expf(m1 - m);
    float inv = 1.f / (w0*l0 + w1*l1);
    w0 *= inv; w1 *= inv;

    float4 o0 = ((const float4*)g_po)[(size_t)row*16 + d4];
    float4 o1 = ((const float4*)g_po)[(size_t)(PO_ROWS + row)*16 + d4];

    uint4 u;
    u.x = f2tf(w0*o0.x + w1*o1.x);
    u.y = f2tf(w0*o0.y + w1*o1.y);
    u.z = f2tf(w0*o0.z + w1*o1.z);
    u.w = f2tf(w0*o0.w + w1*o1.w);

    int q = row & 511, h = (row >> 9) & 15, b = row >> 13;
    ((uint4*)g_ctx)[(size_t)(b*QL + q)*(E/4) + h*(HD/4) + d4] = u;
}

// ---------------- launch ----------------------------------------------------
extern "C" void kernel_launch(void* const* d_in, const int* in_sizes, int n_in,
                              void* d_out, int out_size)
{
    const float* X     = (const float*)d_in[0];
    const float* amask = (const float*)d_in[1];
    const float* kc    = (const float*)d_in[2];
    const float* vc    = (const float*)d_in[3];
    const float* Wq    = (const float*)d_in[4];
    const float* bq    = (const float*)d_in[5];
    const float* Wk    = (const float*)d_in[6];
    const float* bk    = (const float*)d_in[7];
    const float* Wv    = (const float*)d_in[8];
    const float* bv    = (const float*)d_in[9];
    const float* Wo    = (const float*)d_in[10];
    const float* bo    = (const float*)d_in[11];
    float* out = (float*)d_out;

    convert_tf32<<<6144, 256>>>((const float4*)X, (const float4*)Wq,
                                (const float4*)Wk, (const float4*)Wv,
                                (const float4*)Wo);
    {
        int total = BZ*CL*E/4;
        copy_cache<<<(total + 255)/256, 256>>>((const float4*)kc,
                                               (const float4*)vc, out);
    }
    {
        dim3 grid(3*E/128, MROWS/64);        // 24 x 32 = 768 blocks
        gemm_qkv<<<grid, 256>>>(bq, bk, bv, out);
    }
    {
        dim3 grid(16, NH, BZ);               // (qt,chunk) x 16 x 4 = 1024 blocks
        attn<<<grid, 128>>>(amask);
    }
    combine_attn<<<2048, 256>>>();
    {
        dim3 grid(E/128, MROWS/64);          // 8 x 32 = 256 blocks
        gemm_out<<<grid, 256>>>(bo, out);
    }
}

// round 13
// speedup vs baseline: 1.5830x; 1.0256x over previous
#include <cuda_runtime.h>
#include <math.h>

#define BZ   4
#define QL   512
#define CL   1536
#define KVL  2048
#define E    1024
#define NH   16
#define HD   64
#define MROWS (BZ*QL)   // 2048

#define OUT_K ((size_t)MROWS*E)                       // 2097152
#define OUT_V (OUT_K + (size_t)BZ*KVL*E)              // 10485760

#define PO_ROWS (BZ*NH*QL)    // 32768

// ---------------- scratch (tf32 stored as u32) -------------------------------
// g_q and g_kt use the k-pair permuted layout within each 8-group of the E dim:
//   perm8(t) = t<4 ? 2t : 2(t-4)+1   (pairs (t, t+4) -> adjacent (2t, 2t+1))
__device__ unsigned g_xt [MROWS*E];       // X  tf32
__device__ unsigned g_wqt[E*E];           // Wq tf32 [n][k]
__device__ unsigned g_wkt[E*E];
__device__ unsigned g_wvt[E*E];
__device__ unsigned g_wot[E*E];
__device__ unsigned g_q  [MROWS*E];       // Q proj, tf32, 1/8-scaled, PERMUTED
__device__ unsigned g_ctx[MROWS*E];       // attention ctx, tf32 (plain layout)
__device__ unsigned g_kt [(size_t)BZ*KVL*E];  // full K tf32, PERMUTED
__device__ unsigned g_vt [(size_t)BZ*KVL*E];  // full V tf32, plain layout

// split-KV partials
__device__ float g_po[(size_t)2*PO_ROWS*HD];  // unnormalized partial O
__device__ float g_pm[2*PO_ROWS];             // row max
__device__ float g_pl[2*PO_ROWS];             // row sum

// ---------------- helpers ----------------------------------------------------
__device__ __forceinline__ unsigned f2tf(float f) {
    unsigned u;
    asm("cvt.rna.tf32.f32 %0, %1;" : "=r"(u) : "f"(f));
    return u;
}

__device__ __forceinline__ void mma8(float* c,
                                     unsigned a0, unsigned a1, unsigned a2, unsigned a3,
                                     unsigned b0, unsigned b1)
{
    asm volatile(
        "mma.sync.aligned.m16n8k8.row.col.f32.tf32.tf32.f32 "
        "{%0,%1,%2,%3}, {%4,%5,%6,%7}, {%8,%9}, {%0,%1,%2,%3};\n"
        : "+f"(c[0]), "+f"(c[1]), "+f"(c[2]), "+f"(c[3])
        : "r"(a0), "r"(a1), "r"(a2), "r"(a3), "r"(b0), "r"(b1));
}

#define CP16(dst, src) \
    asm volatile("cp.async.cg.shared.global [%0], [%1], 16;\n" \
                 :: "r"(dst), "l"(src))
#define CPCOMMIT() asm volatile("cp.async.commit_group;\n" ::: "memory")
#define CPWAIT(n)  asm volatile("cp.async.wait_group %0;\n" :: "n"(n) : "memory")

// ---------------- convert inputs to tf32 -------------------------------------
__global__ void convert_tf32(const float4* __restrict__ X,
                             const float4* __restrict__ Wq,
                             const float4* __restrict__ Wk,
                             const float4* __restrict__ Wv,
                             const float4* __restrict__ Wo)
{
    int i = blockIdx.x*256 + threadIdx.x;
    const float4* src; uint4* dst; int off;
    if (i < 524288)       { src = X;  dst = (uint4*)g_xt;  off = i; }
    else if (i < 786432)  { src = Wq; dst = (uint4*)g_wqt; off = i - 524288; }
    else if (i < 1048576) { src = Wk; dst = (uint4*)g_wkt; off = i - 786432; }
    else if (i < 1310720) { src = Wv; dst = (uint4*)g_wvt; off = i - 1048576; }
    else                  { src = Wo; dst = (uint4*)g_wot; off = i - 1310720; }
    float4 v = src[off];
    uint4 u;
    u.x = f2tf(v.x); u.y = f2tf(v.y); u.z = f2tf(v.z); u.w = f2tf(v.w);
    dst[off] = u;
}

// ---------------- cache copy: f32 to dout + tf32 to g_kt(perm)/g_vt ----------
__global__ void copy_cache(const float4* __restrict__ kc,
                           const float4* __restrict__ vc,
                           float* __restrict__ dout)
{
    const int per_b = CL*E/4;
    int idx = blockIdx.x*blockDim.x + threadIdx.x;
    if (idx >= BZ*per_b) return;
    int b = idx / per_b, rem = idx - b*per_b;
    size_t d = (size_t)b*(KVL*E/4) + rem;
    float4 k4 = kc[idx], v4 = vc[idx];
    ((float4*)(dout + OUT_K))[d] = k4;
    ((float4*)(dout + OUT_V))[d] = v4;
    // K -> permuted layout: elements 4d..4d+3 land at G+off+{0,2,4,6}
    {
        size_t eb = d*4;
        size_t G  = eb & ~(size_t)7;
        int   off = (eb & 4) ? 1 : 0;
        g_kt[G + off + 0] = f2tf(k4.x);
        g_kt[G + off + 2] = f2tf(k4.y);
        g_kt[G + off + 4] = f2tf(k4.z);
        g_kt[G + off + 6] = f2tf(k4.w);
    }
    uint4 u;
    u.x=f2tf(v4.x); u.y=f2tf(v4.y); u.z=f2tf(v4.z); u.w=f2tf(v4.w);
    ((uint4*)g_vt)[d] = u;
}

// ---------------- tf32 GEMM core (cp.async, 2-stage) -------------------------
// BM=64, BN=128, BK=16, 256 thr, warp grid 2x4, warp tile 32x32, stride 20.
#define GST 20
#define GSTAGE (192*GST)      // (64 A-rows + 128 B-rows) * GST words

__device__ __forceinline__
void gemm_core(const unsigned* __restrict__ AGLOB,
               const unsigned* __restrict__ BGLOB,
               int bm, int nrow0, float acc[2][4][4])
{
    __shared__ __align__(16) unsigned sAB[2*GSTAGE];
    unsigned* Asm[2] = { sAB,          sAB + GSTAGE };
    unsigned* Bsm[2] = { sAB + 64*GST, sAB + GSTAGE + 64*GST };
    unsigned aAddr[2], bAddr[2];
    aAddr[0] = (unsigned)__cvta_generic_to_shared(Asm[0]);
    aAddr[1] = (unsigned)__cvta_generic_to_shared(Asm[1]);
    bAddr[0] = (unsigned)__cvta_generic_to_shared(Bsm[0]);
    bAddr[1] = (unsigned)__cvta_generic_to_shared(Bsm[1]);

    int tid = threadIdx.x;
    int warp = tid >> 5, lane = tid & 31, g = lane >> 2, tig = lane & 3;
    int wm = (warp >> 2)*32, wn = (warp & 3)*32;
    int r0c = tid >> 2, c0c = (tid & 3)*4;     // rows 0..63, col4 0..12
    int r1c = r0c + 64;

    auto issue = [&](int st, int k0) {
        CP16(aAddr[st] + (unsigned)((r0c*GST + c0c)*4),
             AGLOB + (size_t)(bm + r0c)*E + k0 + c0c);
        CP16(bAddr[st] + (unsigned)((r0c*GST + c0c)*4),
             BGLOB + (size_t)(nrow0 + r0c)*E + k0 + c0c);
        CP16(bAddr[st] + (unsigned)((r1c*GST + c0c)*4),
             BGLOB + (size_t)(nrow0 + r1c)*E + k0 + c0c);
    };

    #pragma unroll
    for (int mt = 0; mt < 2; mt++)
        #pragma unroll
        for (int nt = 0; nt < 4; nt++)
            #pragma unroll
            for (int i = 0; i < 4; i++) acc[mt][nt][i] = 0.f;

    issue(0, 0);  CPCOMMIT();
    issue(1, 16); CPCOMMIT();

    for (int kt = 0; kt < 64; kt++) {
        int cur = kt & 1;
        if (kt < 63) { CPWAIT(1); } else { CPWAIT(0); }
        __syncthreads();
        #pragma unroll
        for (int kh = 0; kh < 2; kh++) {
            int kb = kh*8;
            unsigned af[2][4], bf[4][2];
            #pragma unroll
            for (int mt = 0; mt < 2; mt++) {
                int r = wm + mt*16;
                af[mt][0] = Asm[cur][(r+g  )*GST + kb + tig];
                af[mt][1] = Asm[cur][(r+g+8)*GST + kb + tig];
                af[mt][2] = Asm[cur][(r+g  )*GST + kb + tig + 4];
                af[mt][3] = Asm[cur][(r+g+8)*GST + kb + tig + 4];
            }
            #pragma unroll
            for (int nt = 0; nt < 4; nt++) {
                int cidx = wn + nt*8 + g;
                bf[nt][0] = Bsm[cur][cidx*GST + kb + tig];
                bf[nt][1] = Bsm[cur][cidx*GST + kb + tig + 4];
            }
            #pragma unroll
            for (int mt = 0; mt < 2; mt++)
                #pragma unroll
                for (int nt = 0; nt < 4; nt++)
                    mma8(acc[mt][nt], af[mt][0], af[mt][1], af[mt][2],
                         af[mt][3], bf[nt][0], bf[nt][1]);
        }
        __syncthreads();
        if (kt + 2 < 64) { issue(cur, (kt+2)*16); CPCOMMIT(); }
    }
}

// ---------------- QKV projection ---------------------------------------------
__global__ __launch_bounds__(256)
void gemm_qkv(const float* __restrict__ bq, const float* __restrict__ bk,
              const float* __restrict__ bv, float* __restrict__ dout)
{
    int bn = blockIdx.x*128, bm = blockIdx.y*64;
    int seg = bn >> 10;            // 0=Q 1=K 2=V
    int nrow0 = bn & (E-1);
    const unsigned* Bglob = (seg == 0) ? g_wqt : (seg == 1) ? g_wkt : g_wvt;
    const float*    bias  = (seg == 0) ? bq   : (seg == 1) ? bk    : bv;

    float acc[2][4][4];
    gemm_core(g_xt, Bglob, bm, nrow0, acc);

    int tid = threadIdx.x;
    int warp = tid >> 5, lane = tid & 31, g = lane >> 2, tig = lane & 3;
    int wm = (warp >> 2)*32, wn = (warp & 3)*32;

    // permuted positions for columns (2*tig, 2*tig+1) within their 8-group
    int p0 = (tig < 2) ? (4*tig) : (4*(tig-2) + 1);

    #pragma unroll
    for (int mt = 0; mt < 2; mt++) {
        int m = bm + wm + mt*16 + g;
        #pragma unroll
        for (int nt = 0; nt < 4; nt++) {
            int nl = nrow0 + wn + nt*8 + 2*tig;
            float b0 = bias[nl], b1 = bias[nl+1];
            float v0 = acc[mt][nt][0] + b0, v1 = acc[mt][nt][1] + b1;
            float v2 = acc[mt][nt][2] + b0, v3 = acc[mt][nt][3] + b1;
            int base8 = nl & ~7;
            if (seg == 0) {
                // g_q: permuted layout, 1/8 pre-scale
                size_t r0 = (size_t)m*E + base8;
                size_t r1 = (size_t)(m+8)*E + base8;
                g_q[r0 + p0]     = f2tf(v0*0.125f);
                g_q[r0 + p0 + 2] = f2tf(v1*0.125f);
                g_q[r1 + p0]     = f2tf(v2*0.125f);
                g_q[r1 + p0 + 2] = f2tf(v3*0.125f);
            } else {
                float* fbase = dout + (seg == 1 ? OUT_K : OUT_V);
                int ba = m >> 9,      t0 = m & 511;
                int bb = (m+8) >> 9,  t1 = (m+8) & 511;
                size_t ra = ((size_t)(ba*KVL) + CL + t0)*E;
                size_t rb = ((size_t)(bb*KVL) + CL + t1)*E;
                *(float2*)&fbase[ra + nl] = make_float2(v0, v1);
                *(float2*)&fbase[rb + nl] = make_float2(v2, v3);
                if (seg == 1) {
                    // g_kt: permuted layout
                    g_kt[ra + base8 + p0]     = f2tf(v0);
                    g_kt[ra + base8 + p0 + 2] = f2tf(v1);
                    g_kt[rb + base8 + p0]     = f2tf(v2);
                    g_kt[rb + base8 + p0 + 2] = f2tf(v3);
                } else {
                    // g_vt: plain layout
                    uint2 u0; u0.x = f2tf(v0); u0.y = f2tf(v1);
                    uint2 u1; u1.x = f2tf(v2); u1.y = f2tf(v3);
                    *(uint2*)&g_vt[ra + nl] = u0;
                    *(uint2*)&g_vt[rb + nl] = u1;
                }
            }
        }
    }
}

// ---------------- output projection ------------------------------------------
__global__ __launch_bounds__(256)
void gemm_out(const float* __restrict__ bo, float* __restrict__ dout)
{
    int bn = blockIdx.x*128, bm = blockIdx.y*64;

    float acc[2][4][4];
    gemm_core(g_ctx, g_wot, bm, bn, acc);

    int tid = threadIdx.x;
    int warp = tid >> 5, lane = tid & 31, g = lane >> 2, tig = lane & 3;
    int wm = (warp >> 2)*32, wn = (warp & 3)*32;

    #pragma unroll
    for (int mt = 0; mt < 2; mt++) {
        int m = bm + wm + mt*16 + g;
        #pragma unroll
        for (int nt = 0; nt < 4; nt++) {
            int n = bn + wn + nt*8 + 2*tig;
            float b0 = bo[n], b1 = bo[n+1];
            *(float2*)&dout[(size_t)m*E + n] =
                make_float2(acc[mt][nt][0] + b0, acc[mt][nt][1] + b1);
            *(float2*)&dout[(size_t)(m+8)*E + n] =
                make_float2(acc[mt][nt][2] + b0, acc[mt][nt][3] + b1);
        }
    }
}

// ---------------- flash attention: split-KV, Q in SMEM, LDS.64 S-path --------
// Grid (16,16,4): x = qt*2+chunk. 128 thr, 4 warps x 16 q-rows.
// sQ/sK hold k-pair PERMUTED data with swizzle SWKN (conflict-free LDS.64);
// sV keeps the plain layout + SWV (PV path unchanged).
#define SWKN(r,o) ((o) ^ ((((unsigned)(r))&3u)<<3))
#define SWV(r,d)  ((d) ^ ((((unsigned)(r))&3u)<<3))

__global__ __launch_bounds__(128, 4)
void attn(const float* __restrict__ amask)
{
    __shared__ __align__(16) unsigned sQ[64*64];
    __shared__ __align__(16) unsigned sK[64*64];
    __shared__ __align__(16) unsigned sV[64*64];

    int qt    = blockIdx.x >> 1;
    int chunk = blockIdx.x & 1;
    int h = blockIdx.y, b = blockIdx.z;

    int tid  = threadIdx.x;
    int warp = tid >> 5, lane = tid & 31, g = lane >> 2, tig = lane & 3;
    int m0 = warp*16;

    int nkt  = 25 + qt;
    int half = nkt >> 1;
    int t0   = chunk ? half : 0;
    int ntiles = chunk ? (nkt - half) : half;

    unsigned qAddr = (unsigned)__cvta_generic_to_shared(sQ);
    unsigned kAddr = (unsigned)__cvta_generic_to_shared(sK);
    unsigned vAddr = (unsigned)__cvta_generic_to_shared(sV);

    const unsigned* kg = g_kt + ((size_t)b*KVL)*E + h*HD;
    const unsigned* vg = g_vt + ((size_t)b*KVL)*E + h*HD;

    auto issueK = [&](int tile) {
        const unsigned* src = kg + (size_t)tile*64*E;
        #pragma unroll
        for (int i = 0; i < 8; i++) {
            int c = tid + i*128;
            int row = c >> 4, c4 = (c & 15)*4;
            CP16(kAddr + (unsigned)((row*64 + SWKN(row, c4))*4),
                 src + (size_t)row*E + c4);
        }
    };
    auto issueV = [&](int tile) {
        const unsigned* src = vg + (size_t)tile*64*E;
        #pragma unroll
        for (int i = 0; i < 8; i++) {
            int c = tid + i*128;
            int row = c >> 4, c4 = (c & 15)*4;
            CP16(vAddr + (unsigned)((row*64 + SWV(row, c4))*4),
                 src + (size_t)row*E + c4);
        }
    };

    // prologue: Q tile + first K,V — one commit group
    {
        const unsigned* src = g_q + ((size_t)(b*QL + qt*64))*E + h*HD;
        #pragma unroll
        for (int i = 0; i < 8; i++) {
            int c = tid + i*128;
            int row = c >> 4, c4 = (c & 15)*4;
            CP16(qAddr + (unsigned)((row*64 + SWKN(row, c4))*4),
                 src + (size_t)row*E + c4);
        }
    }
    issueK(t0);
    issueV(t0);
    CPCOMMIT();

    float O[8][4];
    #pragma unroll
    for (int nt = 0; nt < 8; nt++)
        #pragma unroll
        for (int i = 0; i < 4; i++) O[nt][i] = 0.f;
    float mi0 = -1e30f, mi1 = -1e30f, li0 = 0.f, li1 = 0.f;

    for (int it = 0; it < ntiles; it++) {
        int kt = t0 + it;
        CPWAIT(0);
        __syncthreads();

        // ---- S = (Q/8) K^T  -- LDS.64 paired fragments from permuted sQ/sK --
        float s[8][4];
        #pragma unroll
        for (int nt = 0; nt < 8; nt++)
            #pragma unroll
            for (int i = 0; i < 4; i++) s[nt][i] = 0.f;
        #pragma unroll
        for (int kc = 0; kc < 8; kc++) {
            int kb = kc*8 + 2*tig;    // permuted pair base: (k=tig, k=tig+4)
            uint2 aLo = *(const uint2*)&sQ[(m0+g  )*64 + SWKN(m0+g,   kb)];
            uint2 aHi = *(const uint2*)&sQ[(m0+g+8)*64 + SWKN(m0+g+8, kb)];
            #pragma unroll
            for (int nt = 0; nt < 8; nt++) {
                int col = nt*8 + g;
                uint2 bp = *(const uint2*)&sK[col*64 + SWKN(col, kb)];
                mma8(s[nt], aLo.x, aHi.x, aLo.y, aHi.y, bp.x, bp.y);
            }
        }

        __syncthreads();                         // sK fully consumed
        if (it + 1 < ntiles) issueK(kt+1);       // K prefetch hides behind softmax+PV

        // ---- mask + online softmax ----
        int c0 = kt*64;
        const float* am = amask + (size_t)b*(CL+QL) + c0;
        bool causal = (chunk == 1) && (it == ntiles-1);
        #pragma unroll
        for (int nt = 0; nt < 8; nt++) {
            int j0 = nt*8 + 2*tig, j1 = j0 + 1;
            float a0 = __ldg(am + j0), a1 = __ldg(am + j1);
            s[nt][0] += a0; s[nt][1] += a1; s[nt][2] += a0; s[nt][3] += a1;
            if (causal) {
                int r0 = CL + qt*64 + m0 + g, r1 = r0 + 8;
                int cj0 = c0 + j0, cj1 = c0 + j1;
                if (cj0 > r0) s[nt][0] = -1e30f;
                if (cj1 > r0) s[nt][1] = -1e30f;
                if (cj0 > r1) s[nt][2] = -1e30f;
                if (cj1 > r1) s[nt][3] = -1e30f;
            }
        }

        float mx0 = -1e30f, mx1 = -1e30f;
        #pragma unroll
        for (int nt = 0; nt < 8; nt++) {
            mx0 = fmaxf(mx0, fmaxf(s[nt][0], s[nt][1]));
            mx1 = fmaxf(mx1, fmaxf(s[nt][2], s[nt][3]));
        }
        mx0 = fmaxf(mx0, __shfl_xor_sync(0xffffffffu, mx0, 1));
        mx0 = fmaxf(mx0, __shfl_xor_sync(0xffffffffu, mx0, 2));
        mx1 = fmaxf(mx1, __shfl_xor_sync(0xffffffffu, mx1, 1));
        mx1 = fmaxf(mx1, __shfl_xor_sync(0xffffffffu, mx1, 2));

        float mn0 = fmaxf(mi0, mx0), mn1 = fmaxf(mi1, mx1);
        float cor0 = __expf(mi0 - mn0), cor1 = __expf(mi1 - mn1);
        mi0 = mn0; mi1 = mn1;

        float sum0 = 0.f, sum1 = 0.f;
        #pragma unroll
        for (int nt = 0; nt < 8; nt++) {
            s[nt][0] = __expf(s[nt][0] - mn0); sum0 += s[nt][0];
            s[nt][1] = __expf(s[nt][1] - mn0); sum0 += s[nt][1];
            s[nt][2] = __expf(s[nt][2] - mn1); sum1 += s[nt][2];
            s[nt][3] = __expf(s[nt][3] - mn1); sum1 += s[nt][3];
        }
        sum0 += __shfl_xor_sync(0xffffffffu, sum0, 1);
        sum0 += __shfl_xor_sync(0xffffffffu, sum0, 2);
        sum1 += __shfl_xor_sync(0xffffffffu, sum1, 1);
        sum1 += __shfl_xor_sync(0xffffffffu, sum1, 2);
        li0 = li0*cor0 + sum0;
        li1 = li1*cor1 + sum1;
        #pragma unroll
        for (int nt = 0; nt < 8; nt++) {
            O[nt][0] *= cor0; O[nt][1] *= cor0;
            O[nt][2] *= cor1; O[nt][3] *= cor1;
        }

        // ---- O += P V  (P via cvt + shfl permutation; V path unchanged) ----
        int l1 = (lane & 28) + (tig >> 1);
        int l2 = l1 + 2;
        bool odd = (tig & 1);
        #pragma unroll
        for (int kc = 0; kc < 8; kc++) {
            unsigned u0 = f2tf(s[kc][0]), u1 = f2tf(s[kc][1]);
            unsigned u2 = f2tf(s[kc][2]), u3 = f2tf(s[kc][3]);
            unsigned s00 = __shfl_sync(0xffffffffu, u0, l1);
            unsigned s01 = __shfl_sync(0xffffffffu, u1, l1);
            unsigned s02 = __shfl_sync(0xffffffffu, u2, l1);
            unsigned s03 = __shfl_sync(0xffffffffu, u3, l1);
            unsigned s10 = __shfl_sync(0xffffffffu, u0, l2);
            unsigned s11 = __shfl_sync(0xffffffffu, u1, l2);
            unsigned s12 = __shfl_sync(0xffffffffu, u2, l2);
            unsigned s13 = __shfl_sync(0xffffffffu, u3, l2);
            unsigned a0 = odd ? s01 : s00;
            unsigned a1 = odd ? s03 : s02;
            unsigned a2 = odd ? s11 : s10;
            unsigned a3 = odd ? s13 : s12;
            int kb = kc*8;
            #pragma unroll
            for (int nt = 0; nt < 8; nt++) {
                int dcol = nt*8 + g;
                unsigned b0 = sV[(kb+tig  )*64 + SWV(kb+tig,   dcol)];
                unsigned b1 = sV[(kb+tig+4)*64 + SWV(kb+tig+4, dcol)];
                mma8(O[nt], a0, a1, a2, a3, b0, b1);
            }
        }

        __syncthreads();                          // sV fully consumed
        if (it + 1 < ntiles) issueV(kt+1);
        CPCOMMIT();                               // group = K(t+1)+V(t+1)
    }

    // ---- write partials (unnormalized O, m, l) ----
    size_t rowbase = ((size_t)(b*NH + h))*QL + qt*64;
    float* po = g_po + ((size_t)chunk*PO_ROWS + rowbase)*HD;
    #pragma unroll
    for (int nt = 0; nt < 8; nt++) {
        int col = nt*8 + 2*tig;
        *(float2*)&po[(size_t)(m0+g)*HD + col]   = make_float2(O[nt][0], O[nt][1]);
        *(float2*)&po[(size_t)(m0+g+8)*HD + col] = make_float2(O[nt][2], O[nt][3]);
    }
    if (tig == 0) {
        size_t mb = (size_t)chunk*PO_ROWS + rowbase;
        g_pm[mb + m0 + g]     = mi0;
        g_pl[mb + m0 + g]     = li0;
        g_pm[mb + m0 + g + 8] = mi1;
        g_pl[mb + m0 + g + 8] = li1;
    }
}

// ---------------- combine split-KV partials -> ctx (tf32, plain layout) ------
__global__ void combine_attn()
{
    int idx = blockIdx.x*256 + threadIdx.x;      // 0 .. 524287
    int d4  = idx & 15;
    int row = idx >> 4;                          // 0 .. 32767

    float m0 = g_pm[row], m1 = g_pm[PO_ROWS + row];
    float l0 = g_pl[row], l1 = g_pl[PO_ROWS + row];
    float m  = fmaxf(m0, m1);
    float w0 = __expf(m0 - m), w1 = __expf(m1 - m);
    float inv = 1.f / (w0*l0 + w1*l1);
    w0 *= inv; w1 *= inv;

    float4 o0 = ((const float4*)g_po)[(size_t)row*16 + d4];
    float4 o1 = ((const float4*)g_po)[(size_t)(PO_ROWS + row)*16 + d4];

    uint4 u;
    u.x = f2tf(w0*o0.x + w1*o1.x);
    u.y = f2tf(w0*o0.y + w1*o1.y);
    u.z = f2tf(w0*o0.z + w1*o1.z);
    u.w = f2tf(w0*o0.w + w1*o1.w);

    int q = row & 511, h = (row >> 9) & 15, b = row >> 13;
    ((uint4*)g_ctx)[(size_t)(b*QL + q)*(E/4) + h*(HD/4) + d4] = u;
}

// ---------------- launch ----------------------------------------------------
extern "C" void kernel_launch(void* const* d_in, const int* in_sizes, int n_in,
                              void* d_out, int out_size)
{
    const float* X     = (const float*)d_in[0];
    const float* amask = (const float*)d_in[1];
    const float* kc    = (const float*)d_in[2];
    const float* vc    = (const float*)d_in[3];
    const float* Wq    = (const float*)d_in[4];
    const float* bq    = (const float*)d_in[5];
    const float* Wk    = (const float*)d_in[6];
    const float* bk    = (const float*)d_in[7];
    const float* Wv    = (const float*)d_in[8];
    const float* bv    = (const float*)d_in[9];
    const float* Wo    = (const float*)d_in[10];
    const float* bo    = (const float*)d_in[11];
    float* out = (float*)d_out;

    convert_tf32<<<6144, 256>>>((const float4*)X, (const float4*)Wq,
                                (const float4*)Wk, (const float4*)Wv,
                                (const float4*)Wo);
    {
        int total = BZ*CL*E/4;
        copy_cache<<<(total + 255)/256, 256>>>((const float4*)kc,
                                               (const float4*)vc, out);
    }
    {
        dim3 grid(3*E/128, MROWS/64);        // 24 x 32 = 768 blocks
        gemm_qkv<<<grid, 256>>>(bq, bk, bv, out);
    }
    {
        dim3 grid(16, NH, BZ);               // (qt,chunk) x 16 x 4 = 1024 blocks
        attn<<<grid, 128>>>(amask);
    }
    combine_attn<<<2048, 256>>>();
    {
        dim3 grid(E/128, MROWS/64);          // 8 x 32 = 256 blocks
        gemm_out<<<grid, 256>>>(bo, out);
    }
}

// round 14
// speedup vs baseline: 1.8046x; 1.1400x over previous
#include <cuda_runtime.h>
#include <math.h>

#define BZ   4
#define QL   512
#define CL   1536
#define KVL  2048
#define E    1024
#define NH   16
#define HD   64
#define MROWS (BZ*QL)   // 2048

#define OUT_K ((size_t)MROWS*E)                       // 2097152
#define OUT_V (OUT_K + (size_t)BZ*KVL*E)              // 10485760

#define PO_ROWS (BZ*NH*QL)    // 32768

// ---------------- scratch (tf32 stored as u32) -------------------------------
// ALL tensor-core operands use the k-pair permuted layout within each 8-group
// of the k dimension: perm8(t) = t<4 ? 2t : 2(t-4)+1  (pairs (t,t+4) adjacent).
// g_vt stays plain (PV's B operand pairs along rows, not columns).
__device__ unsigned g_xt [MROWS*E];       // X  tf32, PERMUTED
__device__ unsigned g_wqt[E*E];           // Wq tf32 [n][k], PERMUTED
__device__ unsigned g_wkt[E*E];           // PERMUTED
__device__ unsigned g_wvt[E*E];           // PERMUTED
__device__ unsigned g_wot[E*E];           // PERMUTED
__device__ unsigned g_q  [MROWS*E];       // Q proj, tf32, 1/8-scaled, PERMUTED
__device__ unsigned g_ctx[MROWS*E];       // attention ctx, tf32, PERMUTED
__device__ unsigned g_kt [(size_t)BZ*KVL*E];  // full K tf32, PERMUTED
__device__ unsigned g_vt [(size_t)BZ*KVL*E];  // full V tf32, plain layout

// split-KV partials
__device__ float g_po[(size_t)2*PO_ROWS*HD];  // unnormalized partial O
__device__ float g_pm[2*PO_ROWS];             // row max
__device__ float g_pl[2*PO_ROWS];             // row sum

// ---------------- helpers ----------------------------------------------------
__device__ __forceinline__ unsigned f2tf(float f) {
    unsigned u;
    asm("cvt.rna.tf32.f32 %0, %1;" : "=r"(u) : "f"(f));
    return u;
}

__device__ __forceinline__ void mma8(float* c,
                                     unsigned a0, unsigned a1, unsigned a2, unsigned a3,
                                     unsigned b0, unsigned b1)
{
    asm volatile(
        "mma.sync.aligned.m16n8k8.row.col.f32.tf32.tf32.f32 "
        "{%0,%1,%2,%3}, {%4,%5,%6,%7}, {%8,%9}, {%0,%1,%2,%3};\n"
        : "+f"(c[0]), "+f"(c[1]), "+f"(c[2]), "+f"(c[3])
        : "r"(a0), "r"(a1), "r"(a2), "r"(a3), "r"(b0), "r"(b1));
}

#define CP16(dst, src) \
    asm volatile("cp.async.cg.shared.global [%0], [%1], 16;\n" \
                 :: "r"(dst), "l"(src))
#define CPCOMMIT() asm volatile("cp.async.commit_group;\n" ::: "memory")
#define CPWAIT(n)  asm volatile("cp.async.wait_group %0;\n" :: "n"(n) : "memory")

// ---------------- convert inputs to tf32 (k-pair permuted) -------------------
// Each float4 covers elements eb..eb+3 of an 8-group: positions off+{0,2,4,6}
// with off = (eb&4)?1:0 — all 4 land in the same 32B sector.
__global__ void convert_tf32(const float4* __restrict__ X,
                             const float4* __restrict__ Wq,
                             const float4* __restrict__ Wk,
                             const float4* __restrict__ Wv,
                             const float4* __restrict__ Wo)
{
    int i = blockIdx.x*256 + threadIdx.x;
    const float4* src; unsigned* dst; int off4;
    if (i < 524288)       { src = X;  dst = g_xt;  off4 = i; }
    else if (i < 786432)  { src = Wq; dst = g_wqt; off4 = i - 524288; }
    else if (i < 1048576) { src = Wk; dst = g_wkt; off4 = i - 786432; }
    else if (i < 1310720) { src = Wv; dst = g_wvt; off4 = i - 1048576; }
    else                  { src = Wo; dst = g_wot; off4 = i - 1310720; }
    float4 v = src[off4];
    size_t eb = (size_t)off4*4;
    size_t G  = eb & ~(size_t)7;
    int   off = (eb & 4) ? 1 : 0;
    dst[G + off + 0] = f2tf(v.x);
    dst[G + off + 2] = f2tf(v.y);
    dst[G + off + 4] = f2tf(v.z);
    dst[G + off + 6] = f2tf(v.w);
}

// ---------------- cache copy: f32 to dout + tf32 to g_kt(perm)/g_vt ----------
__global__ void copy_cache(const float4* __restrict__ kc,
                           const float4* __restrict__ vc,
                           float* __restrict__ dout)
{
    const int per_b = CL*E/4;
    int idx = blockIdx.x*blockDim.x + threadIdx.x;
    if (idx >= BZ*per_b) return;
    int b = idx / per_b, rem = idx - b*per_b;
    size_t d = (size_t)b*(KVL*E/4) + rem;
    float4 k4 = kc[idx], v4 = vc[idx];
    ((float4*)(dout + OUT_K))[d] = k4;
    ((float4*)(dout + OUT_V))[d] = v4;
    // K -> permuted layout
    {
        size_t eb = d*4;
        size_t G  = eb & ~(size_t)7;
        int   off = (eb & 4) ? 1 : 0;
        g_kt[G + off + 0] = f2tf(k4.x);
        g_kt[G + off + 2] = f2tf(k4.y);
        g_kt[G + off + 4] = f2tf(k4.z);
        g_kt[G + off + 6] = f2tf(k4.w);
    }
    uint4 u;
    u.x=f2tf(v4.x); u.y=f2tf(v4.y); u.z=f2tf(v4.z); u.w=f2tf(v4.w);
    ((uint4*)g_vt)[d] = u;
}

// ---------------- tf32 GEMM core (cp.async, 2-stage, LDS.64 fragments) -------
// BM=64, BN=128, BK=16, 256 thr, warp grid 2x4, warp tile 32x32, stride 24.
// Operands are k-pair PERMUTED in global memory -> each thread's fragment pair
// (k=tig, k=tig+4) is adjacent: one LDS.64. GST=24 makes these conflict-free.
#define GST 24
#define GSTAGE (192*GST)      // (64 A-rows + 128 B-rows) * GST words

__device__ __forceinline__
void gemm_core(const unsigned* __restrict__ AGLOB,
               const unsigned* __restrict__ BGLOB,
               int bm, int nrow0, float acc[2][4][4])
{
    __shared__ __align__(16) unsigned sAB[2*GSTAGE];
    unsigned* Asm[2] = { sAB,          sAB + GSTAGE };
    unsigned* Bsm[2] = { sAB + 64*GST, sAB + GSTAGE + 64*GST };
    unsigned aAddr[2], bAddr[2];
    aAddr[0] = (unsigned)__cvta_generic_to_shared(Asm[0]);
    aAddr[1] = (unsigned)__cvta_generic_to_shared(Asm[1]);
    bAddr[0] = (unsigned)__cvta_generic_to_shared(Bsm[0]);
    bAddr[1] = (unsigned)__cvta_generic_to_shared(Bsm[1]);

    int tid = threadIdx.x;
    int warp = tid >> 5, lane = tid & 31, g = lane >> 2, tig = lane & 3;
    int wm = (warp >> 2)*32, wn = (warp & 3)*32;
    int r0c = tid >> 2, c0c = (tid & 3)*4;     // rows 0..63, col4 0..12
    int r1c = r0c + 64;

    auto issue = [&](int st, int k0) {
        CP16(aAddr[st] + (unsigned)((r0c*GST + c0c)*4),
             AGLOB + (size_t)(bm + r0c)*E + k0 + c0c);
        CP16(bAddr[st] + (unsigned)((r0c*GST + c0c)*4),
             BGLOB + (size_t)(nrow0 + r0c)*E + k0 + c0c);
        CP16(bAddr[st] + (unsigned)((r1c*GST + c0c)*4),
             BGLOB + (size_t)(nrow0 + r1c)*E + k0 + c0c);
    };

    #pragma unroll
    for (int mt = 0; mt < 2; mt++)
        #pragma unroll
        for (int nt = 0; nt < 4; nt++)
            #pragma unroll
            for (int i = 0; i < 4; i++) acc[mt][nt][i] = 0.f;

    issue(0, 0);  CPCOMMIT();
    issue(1, 16); CPCOMMIT();

    for (int kt = 0; kt < 64; kt++) {
        int cur = kt & 1;
        if (kt < 63) { CPWAIT(1); } else { CPWAIT(0); }
        __syncthreads();
        #pragma unroll
        for (int kh = 0; kh < 2; kh++) {
            int kb = kh*8 + 2*tig;   // permuted pair base
            uint2 af[2][2];
            #pragma unroll
            for (int mt = 0; mt < 2; mt++) {
                int r = wm + mt*16;
                af[mt][0] = *(const uint2*)&Asm[cur][(r+g  )*GST + kb];
                af[mt][1] = *(const uint2*)&Asm[cur][(r+g+8)*GST + kb];
            }
            uint2 bf[4];
            #pragma unroll
            for (int nt = 0; nt < 4; nt++) {
                int cidx = wn + nt*8 + g;
                bf[nt] = *(const uint2*)&Bsm[cur][cidx*GST + kb];
            }
            #pragma unroll
            for (int mt = 0; mt < 2; mt++)
                #pragma unroll
                for (int nt = 0; nt < 4; nt++)
                    mma8(acc[mt][nt], af[mt][0].x, af[mt][1].x,
                         af[mt][0].y, af[mt][1].y, bf[nt].x, bf[nt].y);
        }
        __syncthreads();
        if (kt + 2 < 64) { issue(cur, (kt+2)*16); CPCOMMIT(); }
    }
}

// ---------------- QKV projection ---------------------------------------------
__global__ __launch_bounds__(256)
void gemm_qkv(const float* __restrict__ bq, const float* __restrict__ bk,
              const float* __restrict__ bv, float* __restrict__ dout)
{
    int bn = blockIdx.x*128, bm = blockIdx.y*64;
    int seg = bn >> 10;            // 0=Q 1=K 2=V
    int nrow0 = bn & (E-1);
    const unsigned* Bglob = (seg == 0) ? g_wqt : (seg == 1) ? g_wkt : g_wvt;
    const float*    bias  = (seg == 0) ? bq   : (seg == 1) ? bk    : bv;

    float acc[2][4][4];
    gemm_core(g_xt, Bglob, bm, nrow0, acc);

    int tid = threadIdx.x;
    int warp = tid >> 5, lane = tid & 31, g = lane >> 2, tig = lane & 3;
    int wm = (warp >> 2)*32, wn = (warp & 3)*32;

    // permuted positions for columns (2*tig, 2*tig+1) within their 8-group
    int p0 = (tig < 2) ? (4*tig) : (4*(tig-2) + 1);

    #pragma unroll
    for (int mt = 0; mt < 2; mt++) {
        int m = bm + wm + mt*16 + g;
        #pragma unroll
        for (int nt = 0; nt < 4; nt++) {
            int nl = nrow0 + wn + nt*8 + 2*tig;
            float b0 = bias[nl], b1 = bias[nl+1];
            float v0 = acc[mt][nt][0] + b0, v1 = acc[mt][nt][1] + b1;
            float v2 = acc[mt][nt][2] + b0, v3 = acc[mt][nt][3] + b1;
            int base8 = nl & ~7;
            if (seg == 0) {
                // g_q: permuted layout, 1/8 pre-scale
                size_t r0 = (size_t)m*E + base8;
                size_t r1 = (size_t)(m+8)*E + base8;
                g_q[r0 + p0]     = f2tf(v0*0.125f);
                g_q[r0 + p0 + 2] = f2tf(v1*0.125f);
                g_q[r1 + p0]     = f2tf(v2*0.125f);
                g_q[r1 + p0 + 2] = f2tf(v3*0.125f);
            } else {
                float* fbase = dout + (seg == 1 ? OUT_K : OUT_V);
                int ba = m >> 9,      t0 = m & 511;
                int bb = (m+8) >> 9,  t1 = (m+8) & 511;
                size_t ra = ((size_t)(ba*KVL) + CL + t0)*E;
                size_t rb = ((size_t)(bb*KVL) + CL + t1)*E;
                *(float2*)&fbase[ra + nl] = make_float2(v0, v1);
                *(float2*)&fbase[rb + nl] = make_float2(v2, v3);
                if (seg == 1) {
                    g_kt[ra + base8 + p0]     = f2tf(v0);
                    g_kt[ra + base8 + p0 + 2] = f2tf(v1);
                    g_kt[rb + base8 + p0]     = f2tf(v2);
                    g_kt[rb + base8 + p0 + 2] = f2tf(v3);
                } else {
                    uint2 u0; u0.x = f2tf(v0); u0.y = f2tf(v1);
                    uint2 u1; u1.x = f2tf(v2); u1.y = f2tf(v3);
                    *(uint2*)&g_vt[ra + nl] = u0;
                    *(uint2*)&g_vt[rb + nl] = u1;
                }
            }
        }
    }
}

// ---------------- output projection ------------------------------------------
__global__ __launch_bounds__(256)
void gemm_out(const float* __restrict__ bo, float* __restrict__ dout)
{
    int bn = blockIdx.x*128, bm = blockIdx.y*64;

    float acc[2][4][4];
    gemm_core(g_ctx, g_wot, bm, bn, acc);

    int tid = threadIdx.x;
    int warp = tid >> 5, lane = tid & 31, g = lane >> 2, tig = lane & 3;
    int wm = (warp >> 2)*32, wn = (warp & 3)*32;

    #pragma unroll
    for (int mt = 0; mt < 2; mt++) {
        int m = bm + wm + mt*16 + g;
        #pragma unroll
        for (int nt = 0; nt < 4; nt++) {
            int n = bn + wn + nt*8 + 2*tig;
            float b0 = bo[n], b1 = bo[n+1];
            *(float2*)&dout[(size_t)m*E + n] =
                make_float2(acc[mt][nt][0] + b0, acc[mt][nt][1] + b1);
            *(float2*)&dout[(size_t)(m+8)*E + n] =
                make_float2(acc[mt][nt][2] + b0, acc[mt][nt][3] + b1);
        }
    }
}

// ---------------- flash attention: split-KV, Q in SMEM, LDS.64 S-path --------
#define SWKN(r,o) ((o) ^ ((((unsigned)(r))&3u)<<3))
#define SWV(r,d)  ((d) ^ ((((unsigned)(r))&3u)<<3))

__global__ __launch_bounds__(128, 4)
void attn(const float* __restrict__ amask)
{
    __shared__ __align__(16) unsigned sQ[64*64];
    __shared__ __align__(16) unsigned sK[64*64];
    __shared__ __align__(16) unsigned sV[64*64];

    int qt    = blockIdx.x >> 1;
    int chunk = blockIdx.x & 1;
    int h = blockIdx.y, b = blockIdx.z;

    int tid  = threadIdx.x;
    int warp = tid >> 5, lane = tid & 31, g = lane >> 2, tig = lane & 3;
    int m0 = warp*16;

    int nkt  = 25 + qt;
    int half = nkt >> 1;
    int t0   = chunk ? half : 0;
    int ntiles = chunk ? (nkt - half) : half;

    unsigned qAddr = (unsigned)__cvta_generic_to_shared(sQ);
    unsigned kAddr = (unsigned)__cvta_generic_to_shared(sK);
    unsigned vAddr = (unsigned)__cvta_generic_to_shared(sV);

    const unsigned* kg = g_kt + ((size_t)b*KVL)*E + h*HD;
    const unsigned* vg = g_vt + ((size_t)b*KVL)*E + h*HD;

    auto issueK = [&](int tile) {
        const unsigned* src = kg + (size_t)tile*64*E;
        #pragma unroll
        for (int i = 0; i < 8; i++) {
            int c = tid + i*128;
            int row = c >> 4, c4 = (c & 15)*4;
            CP16(kAddr + (unsigned)((row*64 + SWKN(row, c4))*4),
                 src + (size_t)row*E + c4);
        }
    };
    auto issueV = [&](int tile) {
        const unsigned* src = vg + (size_t)tile*64*E;
        #pragma unroll
        for (int i = 0; i < 8; i++) {
            int c = tid + i*128;
            int row = c >> 4, c4 = (c & 15)*4;
            CP16(vAddr + (unsigned)((row*64 + SWV(row, c4))*4),
                 src + (size_t)row*E + c4);
        }
    };

    // prologue: Q tile + first K,V — one commit group
    {
        const unsigned* src = g_q + ((size_t)(b*QL + qt*64))*E + h*HD;
        #pragma unroll
        for (int i = 0; i < 8; i++) {
            int c = tid + i*128;
            int row = c >> 4, c4 = (c & 15)*4;
            CP16(qAddr + (unsigned)((row*64 + SWKN(row, c4))*4),
                 src + (size_t)row*E + c4);
        }
    }
    issueK(t0);
    issueV(t0);
    CPCOMMIT();

    float O[8][4];
    #pragma unroll
    for (int nt = 0; nt < 8; nt++)
        #pragma unroll
        for (int i = 0; i < 4; i++) O[nt][i] = 0.f;
    float mi0 = -1e30f, mi1 = -1e30f, li0 = 0.f, li1 = 0.f;

    for (int it = 0; it < ntiles; it++) {
        int kt = t0 + it;
        CPWAIT(0);
        __syncthreads();

        // ---- S = (Q/8) K^T  -- LDS.64 paired fragments from permuted sQ/sK --
        float s[8][4];
        #pragma unroll
        for (int nt = 0; nt < 8; nt++)
            #pragma unroll
            for (int i = 0; i < 4; i++) s[nt][i] = 0.f;
        #pragma unroll
        for (int kc = 0; kc < 8; kc++) {
            int kb = kc*8 + 2*tig;    // permuted pair base: (k=tig, k=tig+4)
            uint2 aLo = *(const uint2*)&sQ[(m0+g  )*64 + SWKN(m0+g,   kb)];
            uint2 aHi = *(const uint2*)&sQ[(m0+g+8)*64 + SWKN(m0+g+8, kb)];
            #pragma unroll
            for (int nt = 0; nt < 8; nt++) {
                int col = nt*8 + g;
                uint2 bp = *(const uint2*)&sK[col*64 + SWKN(col, kb)];
                mma8(s[nt], aLo.x, aHi.x, aLo.y, aHi.y, bp.x, bp.y);
            }
        }

        __syncthreads();                         // sK fully consumed
        if (it + 1 < ntiles) issueK(kt+1);       // K prefetch hides behind softmax+PV

        // ---- mask + online softmax ----
        int c0 = kt*64;
        const float* am = amask + (size_t)b*(CL+QL) + c0;
        bool causal = (chunk == 1) && (it == ntiles-1);
        #pragma unroll
        for (int nt = 0; nt < 8; nt++) {
            int j0 = nt*8 + 2*tig, j1 = j0 + 1;
            float a0 = __ldg(am + j0), a1 = __ldg(am + j1);
            s[nt][0] += a0; s[nt][1] += a1; s[nt][2] += a0; s[nt][3] += a1;
            if (causal) {
                int r0 = CL + qt*64 + m0 + g, r1 = r0 + 8;
                int cj0 = c0 + j0, cj1 = c0 + j1;
                if (cj0 > r0) s[nt][0] = -1e30f;
                if (cj1 > r0) s[nt][1] = -1e30f;
                if (cj0 > r1) s[nt][2] = -1e30f;
                if (cj1 > r1) s[nt][3] = -1e30f;
            }
        }

        float mx0 = -1e30f, mx1 = -1e30f;
        #pragma unroll
        for (int nt = 0; nt < 8; nt++) {
            mx0 = fmaxf(mx0, fmaxf(s[nt][0], s[nt][1]));
            mx1 = fmaxf(mx1, fmaxf(s[nt][2], s[nt][3]));
        }
        mx0 = fmaxf(mx0, __shfl_xor_sync(0xffffffffu, mx0, 1));
        mx0 = fmaxf(mx0, __shfl_xor_sync(0xffffffffu, mx0, 2));
        mx1 = fmaxf(mx1, __shfl_xor_sync(0xffffffffu, mx1, 1));
        mx1 = fmaxf(mx1, __shfl_xor_sync(0xffffffffu, mx1, 2));

        float mn0 = fmaxf(mi0, mx0), mn1 = fmaxf(mi1, mx1);
        float cor0 = __expf(mi0 - mn0), cor1 = __expf(mi1 - mn1);
        mi0 = mn0; mi1 = mn1;

        float sum0 = 0.f, sum1 = 0.f;
        #pragma unroll
        for (int nt = 0; nt < 8; nt++) {
            s[nt][0] = __expf(s[nt][0] - mn0); sum0 += s[nt][0];
            s[nt][1] = __expf(s[nt][1] - mn0); sum0 += s[nt][1];
            s[nt][2] = __expf(s[nt][2] - mn1); sum1 += s[nt][2];
            s[nt][3] = __expf(s[nt][3] - mn1); sum1 += s[nt][3];
        }
        sum0 += __shfl_xor_sync(0xffffffffu, sum0, 1);
        sum0 += __shfl_xor_sync(0xffffffffu, sum0, 2);
        sum1 += __shfl_xor_sync(0xffffffffu, sum1, 1);
        sum1 += __shfl_xor_sync(0xffffffffu, sum1, 2);
        li0 = li0*cor0 + sum0;
        li1 = li1*cor1 + sum1;
        #pragma unroll
        for (int nt = 0; nt < 8; nt++) {
            O[nt][0] *= cor0; O[nt][1] *= cor0;
            O[nt][2] *= cor1; O[nt][3] *= cor1;
        }

        // ---- O += P V  (P via cvt + shfl permutation; V path unchanged) ----
        int l1 = (lane & 28) + (tig >> 1);
        int l2 = l1 + 2;
        bool odd = (tig & 1);
        #pragma unroll
        for (int kc = 0; kc < 8; kc++) {
            unsigned u0 = f2tf(s[kc][0]), u1 = f2tf(s[kc][1]);
            unsigned u2 = f2tf(s[kc][2]), u3 = f2tf(s[kc][3]);
            unsigned s00 = __shfl_sync(0xffffffffu, u0, l1);
            unsigned s01 = __shfl_sync(0xffffffffu, u1, l1);
            unsigned s02 = __shfl_sync(0xffffffffu, u2, l1);
            unsigned s03 = __shfl_sync(0xffffffffu, u3, l1);
            unsigned s10 = __shfl_sync(0xffffffffu, u0, l2);
            unsigned s11 = __shfl_sync(0xffffffffu, u1, l2);
            unsigned s12 = __shfl_sync(0xffffffffu, u2, l2);
            unsigned s13 = __shfl_sync(0xffffffffu, u3, l2);
            unsigned a0 = odd ? s01 : s00;
            unsigned a1 = odd ? s03 : s02;
            unsigned a2 = odd ? s11 : s10;
            unsigned a3 = odd ? s13 : s12;
            int kb = kc*8;
            #pragma unroll
            for (int nt = 0; nt < 8; nt++) {
                int dcol = nt*8 + g;
                unsigned b0 = sV[(kb+tig  )*64 + SWV(kb+tig,   dcol)];
                unsigned b1 = sV[(kb+tig+4)*64 + SWV(kb+tig+4, dcol)];
                mma8(O[nt], a0, a1, a2, a3, b0, b1);
            }
        }

        __syncthreads();                          // sV fully consumed
        if (it + 1 < ntiles) issueV(kt+1);
        CPCOMMIT();                               // group = K(t+1)+V(t+1)
    }

    // ---- write partials (unnormalized O, m, l) ----
    size_t rowbase = ((size_t)(b*NH + h))*QL + qt*64;
    float* po = g_po + ((size_t)chunk*PO_ROWS + rowbase)*HD;
    #pragma unroll
    for (int nt = 0; nt < 8; nt++) {
        int col = nt*8 + 2*tig;
        *(float2*)&po[(size_t)(m0+g)*HD + col]   = make_float2(O[nt][0], O[nt][1]);
        *(float2*)&po[(size_t)(m0+g+8)*HD + col] = make_float2(O[nt][2], O[nt][3]);
    }
    if (tig == 0) {
        size_t mb = (size_t)chunk*PO_ROWS + rowbase;
        g_pm[mb + m0 + g]     = mi0;
        g_pl[mb + m0 + g]     = li0;
        g_pm[mb + m0 + g + 8] = mi1;
        g_pl[mb + m0 + g + 8] = li1;
    }
}

// ---------------- combine split-KV partials -> ctx (tf32, PERMUTED) ----------
__global__ void combine_attn()
{
    int idx = blockIdx.x*256 + threadIdx.x;      // 0 .. 524287
    int d4  = idx & 15;
    int row = idx >> 4;                          // 0 .. 32767

    float m0 = g_pm[row], m1 = g_pm[PO_ROWS + row];
    float l0 = g_pl[row], l1 = g_pl[PO_ROWS + row];
    float m  = fmaxf(m0, m1);
    float w0 = __expf(m0 - m), w1 = __expf(m1 - m);
    float inv = 1.f / (w0*l0 + w1*l1);
    w0 *= inv; w1 *= inv;

    float4 o0 = ((const float4*)g_po)[(size_t)row*16 + d4];
    float4 o1 = ((const float4*)g_po)[(size_t)(PO_ROWS + row)*16 + d4];

    int q = row & 511, h = (row >> 9) & 15, b = row >> 13;
    size_t base = (size_t)(b*QL + q)*E + h*HD + d4*4;
    size_t G    = base & ~(size_t)7;
    int   off   = (base & 4) ? 1 : 0;
    g_ctx[G + off + 0] = f2tf(w0*o0.x + w1*o1.x);
    g_ctx[G + off + 2] = f2tf(w0*o0.y + w1*o1.y);
    g_ctx[G + off + 4] = f2tf(w0*o0.z + w1*o1.z);
    g_ctx[G + off + 6] = f2tf(w0*o0.w + w1*o1.w);
}

// ---------------- launch ----------------------------------------------------
extern "C" void kernel_launch(void* const* d_in, const int* in_sizes, int n_in,
                              void* d_out, int out_size)
{
    const float* X     = (const float*)d_in[0];
    const float* amask = (const float*)d_in[1];
    const float* kc    = (const float*)d_in[2];
    const float* vc    = (const float*)d_in[3];
    const float* Wq    = (const float*)d_in[4];
    const float* bq    = (const float*)d_in[5];
    const float* Wk    = (const float*)d_in[6];
    const float* bk    = (const float*)d_in[7];
    const float* Wv    = (const float*)d_in[8];
    const float* bv    = (const float*)d_in[9];
    const float* Wo    = (const float*)d_in[10];
    const float* bo    = (const float*)d_in[11];
    float* out = (float*)d_out;

    convert_tf32<<<6144, 256>>>((const float4*)X, (const float4*)Wq,
                                (const float4*)Wk, (const float4*)Wv,
                                (const float4*)Wo);
    {
        int total = BZ*CL*E/4;
        copy_cache<<<(total + 255)/256, 256>>>((const float4*)kc,
                                               (const float4*)vc, out);
    }
    {
        dim3 grid(3*E/128, MROWS/64);        // 24 x 32 = 768 blocks
        gemm_qkv<<<grid, 256>>>(bq, bk, bv, out);
    }
    {
        dim3 grid(16, NH, BZ);               // (qt,chunk) x 16 x 4 = 1024 blocks
        attn<<<grid, 128>>>(amask);
    }
    combine_attn<<<2048, 256>>>();
    {
        dim3 grid(E/128, MROWS/64);          // 8 x 32 = 256 blocks
        gemm_out<<<grid, 256>>>(bo, out);
    }
}